// round 2
// baseline (speedup 1.0000x reference)
#include <cuda_runtime.h>
#include <math.h>

// Problem constants
#define AA 512
#define BB 32
#define IDIM 256
#define HDIM 512
#define ODIM 1024          // MSG_DIM * VOCAB
#define NROWS (AA * BB)    // 16384

// d_out layout: [logits (A*B*ODIM)] [h_out (NROWS*HDIM)] [c_out (NROWS*HDIM)]
#define LOGITS_OFF 0
#define H_OFF (AA * BB * ODIM)
#define C_OFF (H_OFF + NROWS * HDIM)

// Scratch for x_proj (relu projection), 16384 x 512 fp32 = 32 MB
__device__ float g_xproj[NROWS * HDIM];

__device__ __forceinline__ float sigmoidf_(float x) {
    return 1.0f / (1.0f + __expf(-x));
}

// ---------------------------------------------------------------------------
// Kernel A: per-a GEMM  x_proj[a,b,h] = relu( sum_i x[a,b,i] * w_in[s_a,h,i] + b_in[s_a,h] )
// C(32 x 512) = X(32 x 256) @ W^T(256 x 512), W row-major (512 x 256)
// grid: (HDIM/128, AA), block 256. Tile: M=32, N=128, K=32.
// ---------------------------------------------------------------------------
__global__ void __launch_bounds__(256) k_xproj(
    const float* __restrict__ x, const int* __restrict__ sp,
    const float* __restrict__ w_in, const float* __restrict__ b_in)
{
    const int a  = blockIdx.y;
    const int n0 = blockIdx.x * 128;
    const int s  = sp[a];
    const float* X = x + (size_t)a * BB * IDIM;
    const float* W = w_in + (size_t)s * HDIM * IDIM;

    __shared__ float Xs[32][33];
    __shared__ float Ws[128][33];

    const int tid = threadIdx.x;
    const int tx = tid & 31;        // 32 col groups
    const int ty = tid >> 5;        // 8 row groups
    const int c0 = tx * 4;
    const int r0 = ty * 4;

    float acc[4][4] = {};

    for (int k0 = 0; k0 < IDIM; k0 += 32) {
        #pragma unroll
        for (int i = 0; i < 4; i++) {
            int idx = tid + i * 256;           // 32x32 = 1024 elems
            int r = idx >> 5, k = idx & 31;
            Xs[r][k] = X[r * IDIM + k0 + k];
        }
        #pragma unroll
        for (int i = 0; i < 16; i++) {
            int idx = tid + i * 256;           // 128x32 = 4096 elems
            int r = idx >> 5, k = idx & 31;
            Ws[r][k] = W[(size_t)(n0 + r) * IDIM + k0 + k];
        }
        __syncthreads();

        #pragma unroll
        for (int k = 0; k < 32; k++) {
            float xr[4], wr[4];
            #pragma unroll
            for (int r = 0; r < 4; r++) xr[r] = Xs[r0 + r][k];
            #pragma unroll
            for (int c = 0; c < 4; c++) wr[c] = Ws[c0 + c][k];
            #pragma unroll
            for (int r = 0; r < 4; r++)
                #pragma unroll
                for (int c = 0; c < 4; c++)
                    acc[r][c] += xr[r] * wr[c];
        }
        __syncthreads();
    }

    #pragma unroll
    for (int r = 0; r < 4; r++) {
        int row = a * BB + r0 + r;
        #pragma unroll
        for (int c = 0; c < 4; c++) {
            int h = n0 + c0 + c;
            float v = acc[r][c] + b_in[s * HDIM + h];
            g_xproj[(size_t)row * HDIM + h] = fmaxf(v, 0.0f);
        }
    }
}

// ---------------------------------------------------------------------------
// Kernel B: gates GEMM (i, g, o blocks only; f-gate dead since c0=0) + fused LSTM pointwise.
// For rows r (16384) and cols h (512):
//   gi = xs@w_ih[h]^T,  gg = xs@w_ih[1024+h]^T,  go = xs@w_ih[1536+h]^T  (+biases)
//   c1 = sigmoid(gi)*tanh(gg);  h1 = sigmoid(go)*tanh(c1)
// grid: (HDIM/64, NROWS/64), block 256. Tile M=64, N=64, K=16, 3 B-operands.
// ---------------------------------------------------------------------------
__global__ void __launch_bounds__(256) k_gates_lstm(
    const float* __restrict__ w_ih,
    const float* __restrict__ b_ih, const float* __restrict__ b_hh,
    float* __restrict__ out)
{
    const int n0 = blockIdx.x * 64;   // h tile
    const int m0 = blockIdx.y * 64;   // row tile

    __shared__ float As[64][17];
    __shared__ float Bi[64][17];
    __shared__ float Bg[64][17];
    __shared__ float Bo[64][17];

    const int tid = threadIdx.x;
    const int tx = tid & 15;          // 16 col groups
    const int ty = tid >> 4;          // 16 row groups
    const int c0 = tx * 4;
    const int r0 = ty * 4;

    float ai[4][4] = {}, ag[4][4] = {}, ao[4][4] = {};

    for (int k0 = 0; k0 < HDIM; k0 += 16) {
        #pragma unroll
        for (int i = 0; i < 4; i++) {
            int idx = tid + i * 256;  // 64x16 = 1024
            int r = idx >> 4, k = idx & 15;
            As[r][k] = g_xproj[(size_t)(m0 + r) * HDIM + k0 + k];
            Bi[r][k] = w_ih[(size_t)(n0 + r) * HDIM + k0 + k];
            Bg[r][k] = w_ih[(size_t)(1024 + n0 + r) * HDIM + k0 + k];
            Bo[r][k] = w_ih[(size_t)(1536 + n0 + r) * HDIM + k0 + k];
        }
        __syncthreads();

        #pragma unroll
        for (int k = 0; k < 16; k++) {
            float ar[4], bi_[4], bg_[4], bo_[4];
            #pragma unroll
            for (int r = 0; r < 4; r++) ar[r] = As[r0 + r][k];
            #pragma unroll
            for (int c = 0; c < 4; c++) {
                bi_[c] = Bi[c0 + c][k];
                bg_[c] = Bg[c0 + c][k];
                bo_[c] = Bo[c0 + c][k];
            }
            #pragma unroll
            for (int r = 0; r < 4; r++)
                #pragma unroll
                for (int c = 0; c < 4; c++) {
                    ai[r][c] += ar[r] * bi_[c];
                    ag[r][c] += ar[r] * bg_[c];
                    ao[r][c] += ar[r] * bo_[c];
                }
        }
        __syncthreads();
    }

    float* h_out = out + H_OFF;
    float* c_out = out + C_OFF;

    #pragma unroll
    for (int r = 0; r < 4; r++) {
        int row = m0 + r0 + r;
        #pragma unroll
        for (int c = 0; c < 4; c++) {
            int h = n0 + c0 + c;
            float gi = ai[r][c] + b_ih[h]        + b_hh[h];
            float gg = ag[r][c] + b_ih[1024 + h] + b_hh[1024 + h];
            float go = ao[r][c] + b_ih[1536 + h] + b_hh[1536 + h];
            float ig = sigmoidf_(gi);
            float gv = tanhf(gg);
            float ov = sigmoidf_(go);
            float c1 = ig * gv;                 // f*c0 == 0
            float h1 = ov * tanhf(c1);
            h_out[(size_t)row * HDIM + h] = h1;
            c_out[(size_t)row * HDIM + h] = c1;
        }
    }
}

// ---------------------------------------------------------------------------
// Kernel C: per-a GEMM  logits[a,b,o] = sum_h h1[a*32+b,h] * w_out[s_a,o,h] + b_out[s_a,o]
// C(32 x 1024) = H(32 x 512) @ Wo^T, Wo row-major (1024 x 512)
// grid: (ODIM/128, AA), block 256. Tile: M=32, N=128, K=32.
// ---------------------------------------------------------------------------
__global__ void __launch_bounds__(256) k_logits(
    const int* __restrict__ sp,
    const float* __restrict__ w_out, const float* __restrict__ b_out,
    float* __restrict__ out)
{
    const int a  = blockIdx.y;
    const int n0 = blockIdx.x * 128;
    const int s  = sp[a];
    const float* Hmat = out + H_OFF + (size_t)a * BB * HDIM;
    const float* W = w_out + (size_t)s * ODIM * HDIM;

    __shared__ float Xs[32][33];
    __shared__ float Ws[128][33];

    const int tid = threadIdx.x;
    const int tx = tid & 31;
    const int ty = tid >> 5;
    const int c0 = tx * 4;
    const int r0 = ty * 4;

    float acc[4][4] = {};

    for (int k0 = 0; k0 < HDIM; k0 += 32) {
        #pragma unroll
        for (int i = 0; i < 4; i++) {
            int idx = tid + i * 256;
            int r = idx >> 5, k = idx & 31;
            Xs[r][k] = Hmat[r * HDIM + k0 + k];
        }
        #pragma unroll
        for (int i = 0; i < 16; i++) {
            int idx = tid + i * 256;
            int r = idx >> 5, k = idx & 31;
            Ws[r][k] = W[(size_t)(n0 + r) * HDIM + k0 + k];
        }
        __syncthreads();

        #pragma unroll
        for (int k = 0; k < 32; k++) {
            float xr[4], wr[4];
            #pragma unroll
            for (int r = 0; r < 4; r++) xr[r] = Xs[r0 + r][k];
            #pragma unroll
            for (int c = 0; c < 4; c++) wr[c] = Ws[c0 + c][k];
            #pragma unroll
            for (int r = 0; r < 4; r++)
                #pragma unroll
                for (int c = 0; c < 4; c++)
                    acc[r][c] += xr[r] * wr[c];
        }
        __syncthreads();
    }

    float* logits = out + LOGITS_OFF + (size_t)a * BB * ODIM;
    #pragma unroll
    for (int r = 0; r < 4; r++) {
        int row = r0 + r;
        #pragma unroll
        for (int c = 0; c < 4; c++) {
            int o = n0 + c0 + c;
            logits[(size_t)row * ODIM + o] = acc[r][c] + b_out[s * ODIM + o];
        }
    }
}

// ---------------------------------------------------------------------------
// Launch: inputs (metadata order):
// 0 x, 1 species_indices, 2 w_in, 3 b_in, 4 w_ih, 5 w_hh, 6 b_ih, 7 b_hh, 8 w_out, 9 b_out
// ---------------------------------------------------------------------------
extern "C" void kernel_launch(void* const* d_in, const int* in_sizes, int n_in,
                              void* d_out, int out_size)
{
    const float* x     = (const float*)d_in[0];
    const int*   sp    = (const int*)d_in[1];
    const float* w_in  = (const float*)d_in[2];
    const float* b_in  = (const float*)d_in[3];
    const float* w_ih  = (const float*)d_in[4];
    // d_in[5] = w_hh: unused (h0 == 0)
    const float* b_ih  = (const float*)d_in[6];
    const float* b_hh  = (const float*)d_in[7];
    const float* w_out = (const float*)d_in[8];
    const float* b_out = (const float*)d_in[9];
    float* out = (float*)d_out;

    dim3 blk(256);

    dim3 gA(HDIM / 128, AA);           // 4 x 512
    k_xproj<<<gA, blk>>>(x, sp, w_in, b_in);

    dim3 gB(HDIM / 64, NROWS / 64);    // 8 x 256
    k_gates_lstm<<<gB, blk>>>(w_ih, b_ih, b_hh, out);

    dim3 gC(ODIM / 128, AA);           // 8 x 512
    k_logits<<<gC, blk>>>(sp, w_out, b_out, out);
}

// round 3
// speedup vs baseline: 1.4694x; 1.4694x over previous
#include <cuda_runtime.h>
#include <math.h>

// Problem constants
#define AA 512
#define BB 32
#define IDIM 256
#define HDIM 512
#define ODIM 1024          // MSG_DIM * VOCAB
#define NROWS (AA * BB)    // 16384
#define NGATES 1536        // packed i,g,o (f elided: c0 == 0)

// d_out layout: [logits (A*B*ODIM)] [h_out] [c_out]
#define LOGITS_OFF 0
#define H_OFF (AA * BB * ODIM)
#define C_OFF (H_OFF + NROWS * HDIM)

// Scratch
__device__ float g_xproj[NROWS * HDIM];          // 32 MB
__device__ float g_gates[(size_t)NROWS * NGATES]; // 96 MB

__device__ __forceinline__ float sigmoidf_(float x) {
    return 1.0f / (1.0f + __expf(-x));
}

__device__ __forceinline__ unsigned f2tf32(float f) {
    unsigned r;
    asm("cvt.rna.tf32.f32 %0, %1;" : "=r"(r) : "f"(f));
    return r;
}

__device__ __forceinline__ void mma_tf32(float* c, const unsigned* a, const unsigned* b) {
    asm volatile(
        "mma.sync.aligned.m16n8k8.row.col.f32.tf32.tf32.f32 "
        "{%0,%1,%2,%3}, {%4,%5,%6,%7}, {%8,%9}, {%0,%1,%2,%3};"
        : "+f"(c[0]), "+f"(c[1]), "+f"(c[2]), "+f"(c[3])
        : "r"(a[0]), "r"(a[1]), "r"(a[2]), "r"(a[3]), "r"(b[0]), "r"(b[1]));
}

// ---------------------------------------------------------------------------
// Kernel A: x_proj = relu(X @ W^T + b), per-a (species-gathered weights).
// Per a: C(32 x 512) = X(32 x 256) @ W(512 x 256)^T
// BM=32, BN=128, BK=32; 256 thr (8 warps): warp grid 2(M) x 4(N); warp tile 16x32.
// ---------------------------------------------------------------------------
__global__ void __launch_bounds__(256) k_xproj_mma(
    const float* __restrict__ x, const int* __restrict__ sp,
    const float* __restrict__ w_in, const float* __restrict__ b_in)
{
    const int a  = blockIdx.y;
    const int n0 = blockIdx.x * 128;
    const int s  = sp[a];
    const float* X = x + (size_t)a * BB * IDIM;
    const float* W = w_in + (size_t)s * HDIM * IDIM;

    __shared__ unsigned As[32][33];
    __shared__ unsigned Bs[128][33];

    const int tid  = threadIdx.x;
    const int wid  = tid >> 5;
    const int lane = tid & 31;
    const int wm = wid >> 2;          // 0..1
    const int wn = wid & 3;           // 0..3
    const int lr = lane >> 2;         // 0..7
    const int lc = lane & 3;          // 0..3

    float acc[4][4] = {};             // FN=4 frags of m16n8

    for (int k0 = 0; k0 < IDIM; k0 += 32) {
        {   // X: 32 rows x 8 float4 = 256 -> 1 per thread
            int f = tid;
            int r = f >> 3, c = (f & 7) << 2;
            float4 v = *(const float4*)&X[(size_t)r * IDIM + k0 + c];
            As[r][c+0] = f2tf32(v.x); As[r][c+1] = f2tf32(v.y);
            As[r][c+2] = f2tf32(v.z); As[r][c+3] = f2tf32(v.w);
        }
        #pragma unroll
        for (int i = 0; i < 4; i++) { // W: 128 rows x 8 float4 = 1024 -> 4 per thread
            int f = tid + i * 256;
            int r = f >> 3, c = (f & 7) << 2;
            float4 v = *(const float4*)&W[(size_t)(n0 + r) * IDIM + k0 + c];
            Bs[r][c+0] = f2tf32(v.x); Bs[r][c+1] = f2tf32(v.y);
            Bs[r][c+2] = f2tf32(v.z); Bs[r][c+3] = f2tf32(v.w);
        }
        __syncthreads();

        #pragma unroll
        for (int kk = 0; kk < 4; kk++) {
            const int kb = kk * 8;
            unsigned af[4];
            const int ar = wm * 16;
            af[0] = As[ar + lr    ][kb + lc    ];
            af[1] = As[ar + lr + 8][kb + lc    ];
            af[2] = As[ar + lr    ][kb + lc + 4];
            af[3] = As[ar + lr + 8][kb + lc + 4];
            #pragma unroll
            for (int fn = 0; fn < 4; fn++) {
                const int nb = wn * 32 + fn * 8;
                unsigned bf[2];
                bf[0] = Bs[nb + lr][kb + lc    ];
                bf[1] = Bs[nb + lr][kb + lc + 4];
                mma_tf32(acc[fn], af, bf);
            }
        }
        __syncthreads();
    }

    // Epilogue: relu + bias
    #pragma unroll
    for (int fn = 0; fn < 4; fn++) {
        int col = n0 + wn * 32 + fn * 8 + lc * 2;
        int row = wm * 16 + lr;
        float b0 = b_in[s * HDIM + col];
        float b1 = b_in[s * HDIM + col + 1];
        size_t base0 = (size_t)(a * BB + row)     * HDIM + col;
        size_t base1 = (size_t)(a * BB + row + 8) * HDIM + col;
        g_xproj[base0    ] = fmaxf(acc[fn][0] + b0, 0.0f);
        g_xproj[base0 + 1] = fmaxf(acc[fn][1] + b1, 0.0f);
        g_xproj[base1    ] = fmaxf(acc[fn][2] + b0, 0.0f);
        g_xproj[base1 + 1] = fmaxf(acc[fn][3] + b1, 0.0f);
    }
}

// ---------------------------------------------------------------------------
// Kernel B: packed gates GEMM  G(16384 x 1536) = xproj(16384 x 512) @ Wsel^T
// Wsel row for packed n: n < 512 ? n : n + 512 (skips dead f-gate block).
// BM=128, BN=128, BK=32; 256 thr (8 warps): warp grid 4(M) x 2(N); warp tile 32x64.
// ---------------------------------------------------------------------------
__global__ void __launch_bounds__(256) k_gates_mma(
    const float* __restrict__ w_ih, float* __restrict__ gates)
{
    const int n0 = blockIdx.x * 128;
    const int m0 = blockIdx.y * 128;
    const int wrow0 = (n0 < 512) ? n0 : n0 + 512;  // block-uniform remap

    __shared__ unsigned As[128][33];
    __shared__ unsigned Bs[128][33];

    const int tid  = threadIdx.x;
    const int wid  = tid >> 5;
    const int lane = tid & 31;
    const int wm = wid >> 1;          // 0..3
    const int wn = wid & 1;           // 0..1
    const int lr = lane >> 2;
    const int lc = lane & 3;

    float acc[2][8][4] = {};          // FM=2, FN=8

    for (int k0 = 0; k0 < HDIM; k0 += 32) {
        #pragma unroll
        for (int i = 0; i < 4; i++) { // 128 rows x 8 float4 = 1024 -> 4 per thread
            int f = tid + i * 256;
            int r = f >> 3, c = (f & 7) << 2;
            float4 va = *(const float4*)&g_xproj[(size_t)(m0 + r) * HDIM + k0 + c];
            As[r][c+0] = f2tf32(va.x); As[r][c+1] = f2tf32(va.y);
            As[r][c+2] = f2tf32(va.z); As[r][c+3] = f2tf32(va.w);
            float4 vb = *(const float4*)&w_ih[(size_t)(wrow0 + r) * HDIM + k0 + c];
            Bs[r][c+0] = f2tf32(vb.x); Bs[r][c+1] = f2tf32(vb.y);
            Bs[r][c+2] = f2tf32(vb.z); Bs[r][c+3] = f2tf32(vb.w);
        }
        __syncthreads();

        #pragma unroll
        for (int kk = 0; kk < 4; kk++) {
            const int kb = kk * 8;
            unsigned af[2][4];
            #pragma unroll
            for (int fm = 0; fm < 2; fm++) {
                const int ar = wm * 32 + fm * 16;
                af[fm][0] = As[ar + lr    ][kb + lc    ];
                af[fm][1] = As[ar + lr + 8][kb + lc    ];
                af[fm][2] = As[ar + lr    ][kb + lc + 4];
                af[fm][3] = As[ar + lr + 8][kb + lc + 4];
            }
            unsigned bf[8][2];
            #pragma unroll
            for (int fn = 0; fn < 8; fn++) {
                const int nb = wn * 64 + fn * 8;
                bf[fn][0] = Bs[nb + lr][kb + lc    ];
                bf[fn][1] = Bs[nb + lr][kb + lc + 4];
            }
            #pragma unroll
            for (int fm = 0; fm < 2; fm++)
                #pragma unroll
                for (int fn = 0; fn < 8; fn++)
                    mma_tf32(acc[fm][fn], af[fm], bf[fn]);
        }
        __syncthreads();
    }

    #pragma unroll
    for (int fm = 0; fm < 2; fm++) {
        int row = m0 + wm * 32 + fm * 16 + lr;
        #pragma unroll
        for (int fn = 0; fn < 8; fn++) {
            int col = n0 + wn * 64 + fn * 8 + lc * 2;
            size_t b0 = (size_t)row * NGATES + col;
            size_t b1 = (size_t)(row + 8) * NGATES + col;
            gates[b0    ] = acc[fm][fn][0];
            gates[b0 + 1] = acc[fm][fn][1];
            gates[b1    ] = acc[fm][fn][2];
            gates[b1 + 1] = acc[fm][fn][3];
        }
    }
}

// ---------------------------------------------------------------------------
// Kernel: pointwise LSTM.  c1 = sig(gi)*tanh(gg); h1 = sig(go)*tanh(c1)
// ---------------------------------------------------------------------------
__global__ void __launch_bounds__(256) k_lstm_pw(
    const float* __restrict__ b_ih, const float* __restrict__ b_hh,
    float* __restrict__ out)
{
    int idx = blockIdx.x * 256 + threadIdx.x;
    int row = idx >> 9;          // /512
    int h   = idx & 511;
    size_t g = (size_t)row * NGATES;
    float gi = g_gates[g + h]          + b_ih[h]        + b_hh[h];
    float gg = g_gates[g + 512 + h]    + b_ih[1024 + h] + b_hh[1024 + h];
    float go = g_gates[g + 1024 + h]   + b_ih[1536 + h] + b_hh[1536 + h];
    float c1 = sigmoidf_(gi) * tanhf(gg);
    float h1 = sigmoidf_(go) * tanhf(c1);
    out[H_OFF + idx] = h1;
    out[C_OFF + idx] = c1;
}

// ---------------------------------------------------------------------------
// Kernel C: logits, per-a.  C(32 x 1024) = H(32 x 512) @ Wo(1024 x 512)^T + b
// Same config as kernel A; K=512, N tiles of 128 -> grid (8, 512).
// ---------------------------------------------------------------------------
__global__ void __launch_bounds__(256) k_logits_mma(
    const int* __restrict__ sp,
    const float* __restrict__ w_out, const float* __restrict__ b_out,
    float* __restrict__ out)
{
    const int a  = blockIdx.y;
    const int n0 = blockIdx.x * 128;
    const int s  = sp[a];
    const float* Hmat = out + H_OFF + (size_t)a * BB * HDIM;
    const float* W = w_out + (size_t)s * ODIM * HDIM;

    __shared__ unsigned As[32][33];
    __shared__ unsigned Bs[128][33];

    const int tid  = threadIdx.x;
    const int wid  = tid >> 5;
    const int lane = tid & 31;
    const int wm = wid >> 2;
    const int wn = wid & 3;
    const int lr = lane >> 2;
    const int lc = lane & 3;

    float acc[4][4] = {};

    for (int k0 = 0; k0 < HDIM; k0 += 32) {
        {
            int f = tid;
            int r = f >> 3, c = (f & 7) << 2;
            float4 v = *(const float4*)&Hmat[(size_t)r * HDIM + k0 + c];
            As[r][c+0] = f2tf32(v.x); As[r][c+1] = f2tf32(v.y);
            As[r][c+2] = f2tf32(v.z); As[r][c+3] = f2tf32(v.w);
        }
        #pragma unroll
        for (int i = 0; i < 4; i++) {
            int f = tid + i * 256;
            int r = f >> 3, c = (f & 7) << 2;
            float4 v = *(const float4*)&W[(size_t)(n0 + r) * HDIM + k0 + c];
            Bs[r][c+0] = f2tf32(v.x); Bs[r][c+1] = f2tf32(v.y);
            Bs[r][c+2] = f2tf32(v.z); Bs[r][c+3] = f2tf32(v.w);
        }
        __syncthreads();

        #pragma unroll
        for (int kk = 0; kk < 4; kk++) {
            const int kb = kk * 8;
            unsigned af[4];
            const int ar = wm * 16;
            af[0] = As[ar + lr    ][kb + lc    ];
            af[1] = As[ar + lr + 8][kb + lc    ];
            af[2] = As[ar + lr    ][kb + lc + 4];
            af[3] = As[ar + lr + 8][kb + lc + 4];
            #pragma unroll
            for (int fn = 0; fn < 4; fn++) {
                const int nb = wn * 32 + fn * 8;
                unsigned bf[2];
                bf[0] = Bs[nb + lr][kb + lc    ];
                bf[1] = Bs[nb + lr][kb + lc + 4];
                mma_tf32(acc[fn], af, bf);
            }
        }
        __syncthreads();
    }

    float* logits = out + LOGITS_OFF + (size_t)a * BB * ODIM;
    #pragma unroll
    for (int fn = 0; fn < 4; fn++) {
        int col = n0 + wn * 32 + fn * 8 + lc * 2;
        int row = wm * 16 + lr;
        float b0 = b_out[s * ODIM + col];
        float b1 = b_out[s * ODIM + col + 1];
        size_t base0 = (size_t)row       * ODIM + col;
        size_t base1 = (size_t)(row + 8) * ODIM + col;
        logits[base0    ] = acc[fn][0] + b0;
        logits[base0 + 1] = acc[fn][1] + b1;
        logits[base1    ] = acc[fn][2] + b0;
        logits[base1 + 1] = acc[fn][3] + b1;
    }
}

// ---------------------------------------------------------------------------
// inputs: 0 x, 1 species, 2 w_in, 3 b_in, 4 w_ih, 5 w_hh(unused), 6 b_ih,
//         7 b_hh, 8 w_out, 9 b_out
// ---------------------------------------------------------------------------
extern "C" void kernel_launch(void* const* d_in, const int* in_sizes, int n_in,
                              void* d_out, int out_size)
{
    const float* x     = (const float*)d_in[0];
    const int*   sp    = (const int*)d_in[1];
    const float* w_in  = (const float*)d_in[2];
    const float* b_in  = (const float*)d_in[3];
    const float* w_ih  = (const float*)d_in[4];
    const float* b_ih  = (const float*)d_in[6];
    const float* b_hh  = (const float*)d_in[7];
    const float* w_out = (const float*)d_in[8];
    const float* b_out = (const float*)d_in[9];
    float* out = (float*)d_out;

    float* gates;
    cudaGetSymbolAddress((void**)&gates, g_gates);

    dim3 blk(256);

    dim3 gA(HDIM / 128, AA);            // 4 x 512
    k_xproj_mma<<<gA, blk>>>(x, sp, w_in, b_in);

    dim3 gB(NGATES / 128, NROWS / 128); // 12 x 128
    k_gates_mma<<<gB, blk>>>(w_ih, gates);

    k_lstm_pw<<<NROWS * HDIM / 256, blk>>>(b_ih, b_hh, out);

    dim3 gC(ODIM / 128, AA);            // 8 x 512
    k_logits_mma<<<gC, blk>>>(sp, w_out, b_out, out);
}

// round 4
// speedup vs baseline: 2.2851x; 1.5551x over previous
#include <cuda_runtime.h>
#include <math.h>

// Problem constants
#define AA 512
#define BB 32
#define IDIM 256
#define HDIM 512
#define ODIM 1024          // MSG_DIM * VOCAB
#define NROWS (AA * BB)    // 16384
#define NGATES 1536        // packed i,g,o (f elided: c0 == 0)
#define MAX_TILES 160      // >= 512/4 + 16

// d_out layout: [logits (A*B*ODIM)] [h_out] [c_out]
#define LOGITS_OFF 0
#define H_OFF (AA * BB * ODIM)
#define C_OFF (H_OFF + NROWS * HDIM)

// Scratch
__device__ float g_xproj[NROWS * HDIM];            // 32 MB
__device__ float g_gates[(size_t)NROWS * NGATES];  // 96 MB
__device__ int   g_ord[AA];
__device__ int   g_sched[MAX_TILES][8];            // {species, a0..a3, pad}

__device__ __forceinline__ float sigmoidf_(float x) {
    return 1.0f / (1.0f + __expf(-x));
}

__device__ __forceinline__ unsigned f2tf32(float f) {
    unsigned r;
    asm("cvt.rna.tf32.f32 %0, %1;" : "=r"(r) : "f"(f));
    return r;
}

__device__ __forceinline__ void mma_tf32(float* c, const unsigned* a, const unsigned* b) {
    asm volatile(
        "mma.sync.aligned.m16n8k8.row.col.f32.tf32.tf32.f32 "
        "{%0,%1,%2,%3}, {%4,%5,%6,%7}, {%8,%9}, {%0,%1,%2,%3};"
        : "+f"(c[0]), "+f"(c[1]), "+f"(c[2]), "+f"(c[3])
        : "r"(a[0]), "r"(a[1]), "r"(a[2]), "r"(a[3]), "r"(b[0]), "r"(b[1]));
}

// Swizzled store of 4 consecutive-k floats (k = c4..c4+3) into a tile row.
// Logical (r, k) lives at col ((k&~7) + (k&3)*2 + ((k>>2)&1)) ^ (4*(r&7)).
// Fragment pair (k=kb+lc, k=kb+lc+4) is then adjacent -> one LDS.64, and the
// 32 lanes of a fragment load cover each smem bank-pair exactly twice.
#define STORE_SW(S, r, c4, v) do {                                   \
    int _kb = (c4) & ~7;                                             \
    int _hf = ((c4) >> 2) & 1;                                       \
    unsigned _sw = 4u * ((r) & 7);                                   \
    S[r][(unsigned)(_kb + 0 + _hf) ^ _sw] = f2tf32((v).x);           \
    S[r][(unsigned)(_kb + 2 + _hf) ^ _sw] = f2tf32((v).y);           \
    S[r][(unsigned)(_kb + 4 + _hf) ^ _sw] = f2tf32((v).z);           \
    S[r][(unsigned)(_kb + 6 + _hf) ^ _sw] = f2tf32((v).w);           \
} while (0)

// ---------------------------------------------------------------------------
// Schedule builder: counting-sort a-indices (512) into 16 species buckets,
// emit 128-row tiles (= 4 a's each) per species. One block, 512 threads.
// ---------------------------------------------------------------------------
__global__ void k_build(const int* __restrict__ sp) {
    __shared__ int cnt[16], base[16], off[16], tb[17];
    int t = threadIdx.x;
    if (t < 16) cnt[t] = 0;
    __syncthreads();
    if (t < AA) atomicAdd(&cnt[sp[t]], 1);
    __syncthreads();
    if (t == 0) {
        int a = 0, tc = 0;
        for (int q = 0; q < 16; q++) {
            base[q] = a; off[q] = a; a += cnt[q];
            tb[q] = tc; tc += (cnt[q] + 3) >> 2;
        }
        tb[16] = tc;
    }
    __syncthreads();
    if (t < AA) {
        int s = sp[t];
        int slot = atomicAdd(&off[s], 1);
        g_ord[slot] = t;
    }
    __syncthreads();
    if (t < MAX_TILES) {
        int s = -1;
        for (int q = 0; q < 16; q++)
            if (t >= tb[q] && t < tb[q + 1]) s = q;
        g_sched[t][0] = s;
        if (s >= 0) {
            int ti = t - tb[s];
            #pragma unroll
            for (int j = 0; j < 4; j++) {
                int idx = ti * 4 + j;
                g_sched[t][1 + j] = (idx < cnt[s]) ? g_ord[base[s] + idx] : -1;
            }
        }
    }
}

// ---------------------------------------------------------------------------
// Unified 128x128-tile TF32 MMA GEMM, C(128 x 128) += A(128 x K) @ W^T.
// MODE 0: xproj  A = x (species-gathered rows), W = w_in[s],  relu+bias -> g_xproj
// MODE 1: gates  A = g_xproj (contiguous),      W = w_ih (f-gate skipped) -> g_gates
// MODE 2: logits A = h1 (species-gathered),     W = w_out[s], bias -> out
// 256 threads / 8 warps: warp grid 4(M) x 2(N), warp tile 32 x 64 (fm2 x fn8).
// ---------------------------------------------------------------------------
template <int MODE>
__global__ void __launch_bounds__(256) k_gemm(
    const float* __restrict__ Ain, const float* __restrict__ Wglob,
    const float* __restrict__ bias, float* __restrict__ Cout)
{
    constexpr int K = (MODE == 0) ? IDIM : HDIM;

    const int tid  = threadIdx.x;
    const int wid  = tid >> 5;
    const int lane = tid & 31;
    const int wm = wid >> 1;          // 0..3
    const int wn = wid & 1;           // 0..1
    const int lr = lane >> 2;         // 0..7
    const int lc = lane & 3;          // 0..3
    const int rowin = tid >> 3;       // 0..31 (row within a 32-row group)
    const int c4 = (tid & 7) << 2;    // 0,4,...,28

    __shared__ unsigned As[128][32];
    __shared__ unsigned Bs[128][32];

    int s = 0;
    int aa[4] = {0, 0, 0, 0};
    size_t arow[4];
    const float* Aptr;

    if (MODE == 1) {
        int m0 = blockIdx.y * 128;
        #pragma unroll
        for (int i = 0; i < 4; i++) arow[i] = (size_t)(m0 + i * 32 + rowin);
        Aptr = (const float*)g_xproj;
    } else {
        const int* t = g_sched[blockIdx.y];
        s = t[0];
        if (s < 0) return;
        #pragma unroll
        for (int i = 0; i < 4; i++) aa[i] = t[1 + i];
        #pragma unroll
        for (int i = 0; i < 4; i++) {
            int a = (aa[i] < 0) ? aa[0] : aa[i];     // clamp pad slots (loads only)
            arow[i] = (size_t)a * 32 + rowin;
        }
        Aptr = Ain;
    }

    const int n0 = blockIdx.x * 128;
    const int wr0 = (MODE == 1) ? ((n0 < 512) ? n0 : n0 + 512) : n0;
    const float* W =
        (MODE == 0) ? Wglob + (size_t)s * HDIM * IDIM :
        (MODE == 2) ? Wglob + (size_t)s * ODIM * HDIM : Wglob;

    // prefetch first k-slab
    float4 pa[4], pb[4];
    #pragma unroll
    for (int i = 0; i < 4; i++) {
        pa[i] = *(const float4*)&Aptr[arow[i] * K + c4];
        pb[i] = *(const float4*)&W[(size_t)(wr0 + i * 32 + rowin) * K + c4];
    }

    float acc[2][8][4] = {};

    #pragma unroll
    for (int kt = 0; kt < K / 32; kt++) {
        #pragma unroll
        for (int i = 0; i < 4; i++) {
            int r = rowin + i * 32;
            STORE_SW(As, r, c4, pa[i]);
            STORE_SW(Bs, r, c4, pb[i]);
        }
        __syncthreads();

        if (kt + 1 < K / 32) {
            int k0 = (kt + 1) * 32;
            #pragma unroll
            for (int i = 0; i < 4; i++) {
                pa[i] = *(const float4*)&Aptr[arow[i] * K + k0 + c4];
                pb[i] = *(const float4*)&W[(size_t)(wr0 + i * 32 + rowin) * K + k0 + c4];
            }
        }

        #pragma unroll
        for (int kk = 0; kk < 4; kk++) {
            const unsigned col = (unsigned)(kk * 8 + 2 * lc);
            const unsigned sw  = 4u * lr;
            unsigned af[2][4];
            #pragma unroll
            for (int fm = 0; fm < 2; fm++) {
                int ar = wm * 32 + fm * 16;
                uint2 lo = *(const uint2*)&As[ar + lr    ][col ^ sw];
                uint2 hi = *(const uint2*)&As[ar + lr + 8][col ^ sw];
                af[fm][0] = lo.x; af[fm][1] = hi.x;
                af[fm][2] = lo.y; af[fm][3] = hi.y;
            }
            unsigned bf[8][2];
            #pragma unroll
            for (int fn = 0; fn < 8; fn++) {
                int nb = wn * 64 + fn * 8;
                uint2 b = *(const uint2*)&Bs[nb + lr][col ^ sw];
                bf[fn][0] = b.x; bf[fn][1] = b.y;
            }
            #pragma unroll
            for (int fm = 0; fm < 2; fm++)
                #pragma unroll
                for (int fn = 0; fn < 8; fn++)
                    mma_tf32(acc[fm][fn], af[fm], bf[fn]);
        }
        __syncthreads();
    }

    // Epilogue. Each warp's rows live entirely in a-group wm.
    if (MODE != 1 && aa[wm] < 0) return;

    #pragma unroll
    for (int fm = 0; fm < 2; fm++) {
        size_t grow0;
        if (MODE == 1) grow0 = (size_t)blockIdx.y * 128 + wm * 32 + fm * 16 + lr;
        else           grow0 = (size_t)aa[wm] * 32 + fm * 16 + lr;
        size_t grow1 = grow0 + 8;

        #pragma unroll
        for (int fn = 0; fn < 8; fn++) {
            int col = n0 + wn * 64 + fn * 8 + lc * 2;
            float v00 = acc[fm][fn][0], v01 = acc[fm][fn][1];
            float v10 = acc[fm][fn][2], v11 = acc[fm][fn][3];
            if (MODE == 0) {
                float b0 = bias[s * HDIM + col], b1 = bias[s * HDIM + col + 1];
                g_xproj[grow0 * HDIM + col    ] = fmaxf(v00 + b0, 0.0f);
                g_xproj[grow0 * HDIM + col + 1] = fmaxf(v01 + b1, 0.0f);
                g_xproj[grow1 * HDIM + col    ] = fmaxf(v10 + b0, 0.0f);
                g_xproj[grow1 * HDIM + col + 1] = fmaxf(v11 + b1, 0.0f);
            } else if (MODE == 1) {
                g_gates[grow0 * NGATES + col    ] = v00;
                g_gates[grow0 * NGATES + col + 1] = v01;
                g_gates[grow1 * NGATES + col    ] = v10;
                g_gates[grow1 * NGATES + col + 1] = v11;
            } else {
                float b0 = bias[s * ODIM + col], b1 = bias[s * ODIM + col + 1];
                Cout[grow0 * ODIM + col    ] = v00 + b0;
                Cout[grow0 * ODIM + col + 1] = v01 + b1;
                Cout[grow1 * ODIM + col    ] = v10 + b0;
                Cout[grow1 * ODIM + col + 1] = v11 + b1;
            }
        }
    }
}

// ---------------------------------------------------------------------------
// Pointwise LSTM (float4): c1 = sig(gi)*tanh(gg); h1 = sig(go)*tanh(c1)
// ---------------------------------------------------------------------------
__global__ void __launch_bounds__(256) k_lstm_pw(
    const float* __restrict__ bi, const float* __restrict__ bh,
    float* __restrict__ out)
{
    int i = blockIdx.x * 256 + threadIdx.x;    // float4 index
    int row = i >> 7;                          // 128 float4 per row
    int h = (i & 127) << 2;
    size_t g = (size_t)row * NGATES;
    float4 g1 = *(const float4*)&g_gates[g + h];
    float4 g2 = *(const float4*)&g_gates[g + 512 + h];
    float4 g3 = *(const float4*)&g_gates[g + 1024 + h];
    float4 bi1 = *(const float4*)&bi[h],        bh1 = *(const float4*)&bh[h];
    float4 bi2 = *(const float4*)&bi[1024 + h], bh2 = *(const float4*)&bh[1024 + h];
    float4 bi3 = *(const float4*)&bi[1536 + h], bh3 = *(const float4*)&bh[1536 + h];

    float4 hv, cv;
    {
        float c1 = sigmoidf_(g1.x + bi1.x + bh1.x) * tanhf(g2.x + bi2.x + bh2.x);
        cv.x = c1; hv.x = sigmoidf_(g3.x + bi3.x + bh3.x) * tanhf(c1);
    }
    {
        float c1 = sigmoidf_(g1.y + bi1.y + bh1.y) * tanhf(g2.y + bi2.y + bh2.y);
        cv.y = c1; hv.y = sigmoidf_(g3.y + bi3.y + bh3.y) * tanhf(c1);
    }
    {
        float c1 = sigmoidf_(g1.z + bi1.z + bh1.z) * tanhf(g2.z + bi2.z + bh2.z);
        cv.z = c1; hv.z = sigmoidf_(g3.z + bi3.z + bh3.z) * tanhf(c1);
    }
    {
        float c1 = sigmoidf_(g1.w + bi1.w + bh1.w) * tanhf(g2.w + bi2.w + bh2.w);
        cv.w = c1; hv.w = sigmoidf_(g3.w + bi3.w + bh3.w) * tanhf(c1);
    }
    *(float4*)&out[H_OFF + (size_t)row * HDIM + h] = hv;
    *(float4*)&out[C_OFF + (size_t)row * HDIM + h] = cv;
}

// ---------------------------------------------------------------------------
// inputs: 0 x, 1 species, 2 w_in, 3 b_in, 4 w_ih, 5 w_hh(unused), 6 b_ih,
//         7 b_hh, 8 w_out, 9 b_out
// ---------------------------------------------------------------------------
extern "C" void kernel_launch(void* const* d_in, const int* in_sizes, int n_in,
                              void* d_out, int out_size)
{
    const float* x     = (const float*)d_in[0];
    const int*   sp    = (const int*)d_in[1];
    const float* w_in  = (const float*)d_in[2];
    const float* b_in  = (const float*)d_in[3];
    const float* w_ih  = (const float*)d_in[4];
    const float* b_ih  = (const float*)d_in[6];
    const float* b_hh  = (const float*)d_in[7];
    const float* w_out = (const float*)d_in[8];
    const float* b_out = (const float*)d_in[9];
    float* out = (float*)d_out;

    k_build<<<1, 512>>>(sp);

    k_gemm<0><<<dim3(HDIM / 128, MAX_TILES), 256>>>(x, w_in, b_in, nullptr);

    k_gemm<1><<<dim3(NGATES / 128, NROWS / 128), 256>>>(nullptr, w_ih, nullptr, nullptr);

    k_lstm_pw<<<NROWS * HDIM / 4 / 256, 256>>>(b_ih, b_hh, out);

    k_gemm<2><<<dim3(ODIM / 128, MAX_TILES), 256>>>(out + H_OFF, w_out, b_out, out);
}

// round 5
// speedup vs baseline: 3.3565x; 1.4689x over previous
#include <cuda_runtime.h>
#include <math.h>
#include <stdint.h>

// Problem constants
#define AA 512
#define BB 32
#define IDIM 256
#define HDIM 512
#define ODIM 1024          // MSG_DIM * VOCAB
#define NROWS (AA * BB)    // 16384
#define NGATES 1536        // packed i,g,o (f elided: c0 == 0)
#define MAX_TILES 160

// d_out layout: [logits] [h_out] [c_out]
#define LOGITS_OFF 0
#define H_OFF (AA * BB * ODIM)
#define C_OFF (H_OFF + NROWS * HDIM)

// Scratch (all pre-rounded to TF32 bit patterns stored as float)
__device__ float g_xr[NROWS * IDIM];               // rounded x          16 MB
__device__ float g_win[16 * HDIM * IDIM];          // rounded w_in        8 MB
__device__ float g_wih[NGATES * HDIM];             // rounded packed w_ih 3 MB
__device__ float g_wout[16 * ODIM * HDIM];         // rounded w_out      32 MB
__device__ float g_xproj[NROWS * HDIM];            // rounded xproj, then rounded h1
__device__ float g_gates[(size_t)NROWS * NGATES];  // raw gates          96 MB
__device__ int   g_ord[AA];
__device__ int   g_sched[MAX_TILES][8];            // {species, a0..a3, pad}

__device__ __forceinline__ float sigmoidf_(float x) {
    return 1.0f / (1.0f + __expf(-x));
}
__device__ __forceinline__ unsigned f2tf32(float f) {
    unsigned r;
    asm("cvt.rna.tf32.f32 %0, %1;" : "=r"(r) : "f"(f));
    return r;
}
__device__ __forceinline__ float roundtf(float f) { return __uint_as_float(f2tf32(f)); }

__device__ __forceinline__ void mma_tf32(float* c, const unsigned* a, const unsigned* b) {
    asm volatile(
        "mma.sync.aligned.m16n8k8.row.col.f32.tf32.tf32.f32 "
        "{%0,%1,%2,%3}, {%4,%5,%6,%7}, {%8,%9}, {%0,%1,%2,%3};"
        : "+f"(c[0]), "+f"(c[1]), "+f"(c[2]), "+f"(c[3])
        : "r"(a[0]), "r"(a[1]), "r"(a[2]), "r"(a[3]), "r"(b[0]), "r"(b[1]));
}

__device__ __forceinline__ uint32_t s2u(const void* p) {
    uint32_t a;
    asm("{ .reg .u64 t; cvta.to.shared.u64 t, %1; cvt.u32.u64 %0, t; }" : "=r"(a) : "l"(p));
    return a;
}
__device__ __forceinline__ void cp16(uint32_t dst, const void* src) {
    asm volatile("cp.async.cg.shared.global [%0], [%1], 16;" :: "r"(dst), "l"(src));
}

// ---------------------------------------------------------------------------
// Schedule builder (unchanged from R4): species-bucketed 128-row tiles.
// ---------------------------------------------------------------------------
__global__ void k_build(const int* __restrict__ sp) {
    __shared__ int cnt[16], base[16], off[16], tb[17];
    int t = threadIdx.x;
    if (t < 16) cnt[t] = 0;
    __syncthreads();
    if (t < AA) atomicAdd(&cnt[sp[t]], 1);
    __syncthreads();
    if (t == 0) {
        int a = 0, tc = 0;
        for (int q = 0; q < 16; q++) {
            base[q] = a; off[q] = a; a += cnt[q];
            tb[q] = tc; tc += (cnt[q] + 3) >> 2;
        }
        tb[16] = tc;
    }
    __syncthreads();
    if (t < AA) {
        int s = sp[t];
        int slot = atomicAdd(&off[s], 1);
        g_ord[slot] = t;
    }
    __syncthreads();
    if (t < MAX_TILES) {
        int s = -1;
        for (int q = 0; q < 16; q++)
            if (t >= tb[q] && t < tb[q + 1]) s = q;
        g_sched[t][0] = s;
        if (s >= 0) {
            int ti = t - tb[s];
            #pragma unroll
            for (int j = 0; j < 4; j++) {
                int idx = ti * 4 + j;
                g_sched[t][1 + j] = (idx < cnt[s]) ? g_ord[base[s] + idx] : -1;
            }
        }
    }
}

// ---------------------------------------------------------------------------
// Pre-round x, w_in, w_out, and packed w_ih (i,g,o rows) to TF32.
// ---------------------------------------------------------------------------
#define XR_F4   (NROWS * IDIM / 4)
#define WIN_F4  (16 * HDIM * IDIM / 4)
#define WOUT_F4 (16 * ODIM * HDIM / 4)
#define WIH_F4  (NGATES * HDIM / 4)
#define TOT_F4  (XR_F4 + WIN_F4 + WOUT_F4 + WIH_F4)

__global__ void __launch_bounds__(256) k_round(
    const float4* __restrict__ x, const float4* __restrict__ w_in,
    const float* __restrict__ w_ih, const float4* __restrict__ w_out)
{
    int i = blockIdx.x * 256 + threadIdx.x;
    if (i >= TOT_F4) return;
    float4 v; float4* dst;
    if (i < XR_F4) {
        v = x[i]; dst = (float4*)g_xr + i;
    } else if (i < XR_F4 + WIN_F4) {
        int j = i - XR_F4; v = w_in[j]; dst = (float4*)g_win + j;
    } else if (i < XR_F4 + WIN_F4 + WOUT_F4) {
        int j = i - XR_F4 - WIN_F4; v = w_out[j]; dst = (float4*)g_wout + j;
    } else {
        int j = i - XR_F4 - WIN_F4 - WOUT_F4;
        int r = j >> 7, c = j & 127;                   // 128 float4 per 512-row
        int sr = (r < 512) ? r : r + 512;              // skip dead f-gate block
        v = *(const float4*)&w_ih[(size_t)sr * HDIM + c * 4];
        dst = (float4*)g_wih + j;
    }
    v.x = roundtf(v.x); v.y = roundtf(v.y); v.z = roundtf(v.z); v.w = roundtf(v.w);
    *dst = v;
}

// ---------------------------------------------------------------------------
// Unified pipelined GEMM: C(128 x 256) = A(128 x K) @ W(256 x K)^T.
// cp.async 2-stage double buffer; swizzled smem (chunk c at c^(r&7)).
// 8 warps: warp grid 2(M) x 4(N), warp tile 64 x 64 (fm4 x fn8).
// MODE 0: xproj (species tiles, A=g_xr, W=g_win[s], relu+bias, round -> g_xproj)
// MODE 1: gates (contiguous,   A=g_xproj, W=g_wih packed -> g_gates)
// MODE 2: logits (species tiles, A=g_xproj(h1 rounded), W=g_wout[s], bias -> out)
// ---------------------------------------------------------------------------
template <int K>
__device__ __forceinline__ void load_stage(
    const float* __restrict__ Aptr, const float* __restrict__ W,
    int4 ab, int n0, int tid, int k0, uint32_t aB, uint32_t bB)
{
    #pragma unroll
    for (int i = 0; i < 4; i++) {
        int idx = tid + i * 256, r = idx >> 3, c = idx & 7, p = c ^ (r & 7);
        int g = r >> 5;
        int base = (g == 0) ? ab.x : (g == 1) ? ab.y : (g == 2) ? ab.z : ab.w;
        cp16(aB + r * 128 + p * 16, Aptr + (size_t)(base + (r & 31)) * K + k0 + c * 4);
    }
    #pragma unroll
    for (int i = 0; i < 8; i++) {
        int idx = tid + i * 256, r = idx >> 3, c = idx & 7, p = c ^ (r & 7);
        cp16(bB + r * 128 + p * 16, W + (size_t)(n0 + r) * K + k0 + c * 4);
    }
    asm volatile("cp.async.commit_group;");
}

template <int MODE>
__global__ void __launch_bounds__(256) k_gemm(
    const float* __restrict__ bias, float* __restrict__ Cout)
{
    constexpr int K = (MODE == 0) ? IDIM : HDIM;
    constexpr int NSLAB = K / 32;

    extern __shared__ float sm[];
    float* Abuf[2] = { sm, sm + 128 * 32 };
    float* Bbuf[2] = { sm + 2 * 128 * 32, sm + 2 * 128 * 32 + 256 * 32 };

    const int tid  = threadIdx.x;
    const int wid  = tid >> 5;
    const int lane = tid & 31;
    const int wm = wid >> 2;          // 0..1
    const int wn = wid & 3;           // 0..3
    const int lr = lane >> 2;         // 0..7
    const int lc = lane & 3;          // 0..3

    int s = 0;
    int aa[4] = {0, 0, 0, 0};
    int4 ab;
    const float* Aptr;
    const float* W;
    const int n0 = blockIdx.x * 256;

    if (MODE == 1) {
        int m0 = blockIdx.y * 128;
        ab = make_int4(m0, m0 + 32, m0 + 64, m0 + 96);
        Aptr = (const float*)g_xproj;
        W = (const float*)g_wih;
    } else {
        const int* t = g_sched[blockIdx.y];
        s = t[0];
        if (s < 0) return;
        int b0 = t[1];
        #pragma unroll
        for (int i = 0; i < 4; i++) aa[i] = t[1 + i];
        ab.x = ((aa[0] < 0) ? b0 : aa[0]) * 32;
        ab.y = ((aa[1] < 0) ? b0 : aa[1]) * 32;
        ab.z = ((aa[2] < 0) ? b0 : aa[2]) * 32;
        ab.w = ((aa[3] < 0) ? b0 : aa[3]) * 32;
        Aptr = (MODE == 0) ? (const float*)g_xr : (const float*)g_xproj;
        W = (MODE == 0) ? (const float*)g_win + (size_t)s * HDIM * IDIM
                        : (const float*)g_wout + (size_t)s * ODIM * HDIM;
    }

    uint32_t aB[2] = { s2u(Abuf[0]), s2u(Abuf[1]) };
    uint32_t bB[2] = { s2u(Bbuf[0]), s2u(Bbuf[1]) };

    float acc[4][8][4] = {};

    load_stage<K>(Aptr, W, ab, n0, tid, 0, aB[0], bB[0]);

    for (int kt = 0; kt < NSLAB; kt++) {
        int st = kt & 1;
        if (kt + 1 < NSLAB) {
            load_stage<K>(Aptr, W, ab, n0, tid, (kt + 1) * 32, aB[st ^ 1], bB[st ^ 1]);
            asm volatile("cp.async.wait_group 1;");
        } else {
            asm volatile("cp.async.wait_group 0;");
        }
        __syncthreads();

        const float* At = Abuf[st];
        const float* Bt = Bbuf[st];

        #pragma unroll
        for (int kk = 0; kk < 4; kk++) {
            const int sw0 = ((2 * kk)     ^ lr) * 4 + lc;
            const int sw1 = ((2 * kk + 1) ^ lr) * 4 + lc;
            unsigned af[4][4];
            #pragma unroll
            for (int fm = 0; fm < 4; fm++) {
                int r0 = (wm * 64 + fm * 16 + lr) * 32;
                int r1 = r0 + 8 * 32;
                af[fm][0] = __float_as_uint(At[r0 + sw0]);
                af[fm][1] = __float_as_uint(At[r1 + sw0]);
                af[fm][2] = __float_as_uint(At[r0 + sw1]);
                af[fm][3] = __float_as_uint(At[r1 + sw1]);
            }
            unsigned bf[8][2];
            #pragma unroll
            for (int fn = 0; fn < 8; fn++) {
                int rb = (wn * 64 + fn * 8 + lr) * 32;
                bf[fn][0] = __float_as_uint(Bt[rb + sw0]);
                bf[fn][1] = __float_as_uint(Bt[rb + sw1]);
            }
            #pragma unroll
            for (int fm = 0; fm < 4; fm++)
                #pragma unroll
                for (int fn = 0; fn < 8; fn++)
                    mma_tf32(acc[fm][fn], af[fm], bf[fn]);
        }
        __syncthreads();
    }

    // Epilogue
    #pragma unroll
    for (int fm = 0; fm < 4; fm++) {
        int rl = wm * 64 + fm * 16 + lr;          // 0..127 (row and row+8 same group)
        int grp = rl >> 5;
        if (MODE != 1 && aa[grp] < 0) continue;
        size_t grow0;
        if (MODE == 1) grow0 = (size_t)blockIdx.y * 128 + rl;
        else           grow0 = (size_t)aa[grp] * 32 + (rl & 31);
        size_t grow1 = grow0 + 8;

        #pragma unroll
        for (int fn = 0; fn < 8; fn++) {
            int col = n0 + wn * 64 + fn * 8 + lc * 2;
            float v00 = acc[fm][fn][0], v01 = acc[fm][fn][1];
            float v10 = acc[fm][fn][2], v11 = acc[fm][fn][3];
            if (MODE == 0) {
                float b0 = bias[s * HDIM + col], b1 = bias[s * HDIM + col + 1];
                g_xproj[grow0 * HDIM + col    ] = roundtf(fmaxf(v00 + b0, 0.0f));
                g_xproj[grow0 * HDIM + col + 1] = roundtf(fmaxf(v01 + b1, 0.0f));
                g_xproj[grow1 * HDIM + col    ] = roundtf(fmaxf(v10 + b0, 0.0f));
                g_xproj[grow1 * HDIM + col + 1] = roundtf(fmaxf(v11 + b1, 0.0f));
            } else if (MODE == 1) {
                g_gates[grow0 * NGATES + col    ] = v00;
                g_gates[grow0 * NGATES + col + 1] = v01;
                g_gates[grow1 * NGATES + col    ] = v10;
                g_gates[grow1 * NGATES + col + 1] = v11;
            } else {
                float b0 = bias[s * ODIM + col], b1 = bias[s * ODIM + col + 1];
                Cout[grow0 * ODIM + col    ] = v00 + b0;
                Cout[grow0 * ODIM + col + 1] = v01 + b1;
                Cout[grow1 * ODIM + col    ] = v10 + b0;
                Cout[grow1 * ODIM + col + 1] = v11 + b1;
            }
        }
    }
}

// ---------------------------------------------------------------------------
// Pointwise LSTM. Also writes TF32-rounded h1 into g_xproj (A of logits).
// ---------------------------------------------------------------------------
__global__ void __launch_bounds__(256) k_lstm_pw(
    const float* __restrict__ bi, const float* __restrict__ bh,
    float* __restrict__ out)
{
    int i = blockIdx.x * 256 + threadIdx.x;    // float4 index
    int row = i >> 7;
    int h = (i & 127) << 2;
    size_t g = (size_t)row * NGATES;
    float4 g1 = *(const float4*)&g_gates[g + h];
    float4 g2 = *(const float4*)&g_gates[g + 512 + h];
    float4 g3 = *(const float4*)&g_gates[g + 1024 + h];
    float4 bi1 = *(const float4*)&bi[h],        bh1 = *(const float4*)&bh[h];
    float4 bi2 = *(const float4*)&bi[1024 + h], bh2 = *(const float4*)&bh[1024 + h];
    float4 bi3 = *(const float4*)&bi[1536 + h], bh3 = *(const float4*)&bh[1536 + h];

    float4 hv, cv, hr;
    {
        float c1 = sigmoidf_(g1.x + bi1.x + bh1.x) * tanhf(g2.x + bi2.x + bh2.x);
        cv.x = c1; hv.x = sigmoidf_(g3.x + bi3.x + bh3.x) * tanhf(c1); hr.x = roundtf(hv.x);
    }
    {
        float c1 = sigmoidf_(g1.y + bi1.y + bh1.y) * tanhf(g2.y + bi2.y + bh2.y);
        cv.y = c1; hv.y = sigmoidf_(g3.y + bi3.y + bh3.y) * tanhf(c1); hr.y = roundtf(hv.y);
    }
    {
        float c1 = sigmoidf_(g1.z + bi1.z + bh1.z) * tanhf(g2.z + bi2.z + bh2.z);
        cv.z = c1; hv.z = sigmoidf_(g3.z + bi3.z + bh3.z) * tanhf(c1); hr.z = roundtf(hv.z);
    }
    {
        float c1 = sigmoidf_(g1.w + bi1.w + bh1.w) * tanhf(g2.w + bi2.w + bh2.w);
        cv.w = c1; hv.w = sigmoidf_(g3.w + bi3.w + bh3.w) * tanhf(c1); hr.w = roundtf(hv.w);
    }
    size_t o = (size_t)row * HDIM + h;
    *(float4*)&out[H_OFF + o] = hv;
    *(float4*)&out[C_OFF + o] = cv;
    *(float4*)&g_xproj[o] = hr;               // gates GEMM is done; safe reuse
}

// ---------------------------------------------------------------------------
// inputs: 0 x, 1 species, 2 w_in, 3 b_in, 4 w_ih, 5 w_hh(unused), 6 b_ih,
//         7 b_hh, 8 w_out, 9 b_out
// ---------------------------------------------------------------------------
extern "C" void kernel_launch(void* const* d_in, const int* in_sizes, int n_in,
                              void* d_out, int out_size)
{
    const float* x     = (const float*)d_in[0];
    const int*   sp    = (const int*)d_in[1];
    const float* w_in  = (const float*)d_in[2];
    const float* b_in  = (const float*)d_in[3];
    const float* w_ih  = (const float*)d_in[4];
    const float* b_ih  = (const float*)d_in[6];
    const float* b_hh  = (const float*)d_in[7];
    const float* w_out = (const float*)d_in[8];
    const float* b_out = (const float*)d_in[9];
    float* out = (float*)d_out;

    const int SMEM = (2 * 128 * 32 + 2 * 256 * 32) * 4;   // 96 KB
    static bool attr_done = false;
    if (!attr_done) {
        cudaFuncSetAttribute(k_gemm<0>, cudaFuncAttributeMaxDynamicSharedMemorySize, SMEM);
        cudaFuncSetAttribute(k_gemm<1>, cudaFuncAttributeMaxDynamicSharedMemorySize, SMEM);
        cudaFuncSetAttribute(k_gemm<2>, cudaFuncAttributeMaxDynamicSharedMemorySize, SMEM);
        attr_done = true;
    }

    k_build<<<1, 512>>>(sp);

    k_round<<<(TOT_F4 + 255) / 256, 256>>>(
        (const float4*)x, (const float4*)w_in, w_ih, (const float4*)w_out);

    k_gemm<0><<<dim3(HDIM / 256, MAX_TILES), 256, SMEM>>>(b_in, nullptr);

    k_gemm<1><<<dim3(NGATES / 256, NROWS / 128), 256, SMEM>>>(nullptr, nullptr);

    k_lstm_pw<<<NROWS * HDIM / 4 / 256, 256>>>(b_ih, b_hh, out);

    k_gemm<2><<<dim3(ODIM / 256, MAX_TILES), 256, SMEM>>>(b_out, out);
}

// round 6
// speedup vs baseline: 3.8492x; 1.1468x over previous
#include <cuda_runtime.h>
#include <math.h>
#include <stdint.h>

// Problem constants
#define AA 512
#define BB 32
#define IDIM 256
#define HDIM 512
#define ODIM 1024          // MSG_DIM * VOCAB
#define NROWS (AA * BB)    // 16384
#define NGATES 1536        // packed i,g,o (f elided: c0 == 0)
#define MAX_TILES 160

// d_out layout: [logits] [h_out] [c_out]
#define LOGITS_OFF 0
#define H_OFF (AA * BB * ODIM)
#define C_OFF (H_OFF + NROWS * HDIM)

// Scratch (pre-rounded TF32 bit patterns stored as float)
__device__ float g_xr[NROWS * IDIM];
__device__ float g_win[16 * HDIM * IDIM];
__device__ float g_wih[NGATES * HDIM];
__device__ float g_wout[16 * ODIM * HDIM];
__device__ float g_xproj[NROWS * HDIM];            // rounded xproj, then rounded h1
__device__ float g_gates[(size_t)NROWS * NGATES];
__device__ int   g_ord[AA];
__device__ int   g_sched[MAX_TILES][8];            // {species, a0..a3, pad}

__device__ __forceinline__ float sigmoidf_(float x) {
    return 1.0f / (1.0f + __expf(-x));
}
__device__ __forceinline__ unsigned f2tf32(float f) {
    unsigned r;
    asm("cvt.rna.tf32.f32 %0, %1;" : "=r"(r) : "f"(f));
    return r;
}
__device__ __forceinline__ float roundtf(float f) { return __uint_as_float(f2tf32(f)); }

__device__ __forceinline__ void mma_tf32(float* c, const unsigned* a, const unsigned* b) {
    asm volatile(
        "mma.sync.aligned.m16n8k8.row.col.f32.tf32.tf32.f32 "
        "{%0,%1,%2,%3}, {%4,%5,%6,%7}, {%8,%9}, {%0,%1,%2,%3};"
        : "+f"(c[0]), "+f"(c[1]), "+f"(c[2]), "+f"(c[3])
        : "r"(a[0]), "r"(a[1]), "r"(a[2]), "r"(a[3]), "r"(b[0]), "r"(b[1]));
}

__device__ __forceinline__ uint32_t s2u(const void* p) {
    uint32_t a;
    asm("{ .reg .u64 t; cvta.to.shared.u64 t, %1; cvt.u32.u64 %0, t; }" : "=r"(a) : "l"(p));
    return a;
}
__device__ __forceinline__ void cp16(uint32_t dst, const void* src) {
    asm volatile("cp.async.cg.shared.global [%0], [%1], 16;" :: "r"(dst), "l"(src));
}

// ---------------------------------------------------------------------------
// Schedule builder: species-bucketed 128-row tiles.
// ---------------------------------------------------------------------------
__global__ void k_build(const int* __restrict__ sp) {
    __shared__ int cnt[16], base[16], off[16], tb[17];
    int t = threadIdx.x;
    if (t < 16) cnt[t] = 0;
    __syncthreads();
    if (t < AA) atomicAdd(&cnt[sp[t]], 1);
    __syncthreads();
    if (t == 0) {
        int a = 0, tc = 0;
        for (int q = 0; q < 16; q++) {
            base[q] = a; off[q] = a; a += cnt[q];
            tb[q] = tc; tc += (cnt[q] + 3) >> 2;
        }
        tb[16] = tc;
    }
    __syncthreads();
    if (t < AA) {
        int s = sp[t];
        int slot = atomicAdd(&off[s], 1);
        g_ord[slot] = t;
    }
    __syncthreads();
    if (t < MAX_TILES) {
        int s = -1;
        for (int q = 0; q < 16; q++)
            if (t >= tb[q] && t < tb[q + 1]) s = q;
        g_sched[t][0] = s;
        if (s >= 0) {
            int ti = t - tb[s];
            #pragma unroll
            for (int j = 0; j < 4; j++) {
                int idx = ti * 4 + j;
                g_sched[t][1 + j] = (idx < cnt[s]) ? g_ord[base[s] + idx] : -1;
            }
        }
    }
}

// ---------------------------------------------------------------------------
// Pre-round x, w_in, w_out, packed w_ih to TF32.
// ---------------------------------------------------------------------------
#define XR_F4   (NROWS * IDIM / 4)
#define WIN_F4  (16 * HDIM * IDIM / 4)
#define WOUT_F4 (16 * ODIM * HDIM / 4)
#define WIH_F4  (NGATES * HDIM / 4)
#define TOT_F4  (XR_F4 + WIN_F4 + WOUT_F4 + WIH_F4)

__global__ void __launch_bounds__(256) k_round(
    const float4* __restrict__ x, const float4* __restrict__ w_in,
    const float* __restrict__ w_ih, const float4* __restrict__ w_out)
{
    int i = blockIdx.x * 256 + threadIdx.x;
    if (i >= TOT_F4) return;
    float4 v; float4* dst;
    if (i < XR_F4) {
        v = x[i]; dst = (float4*)g_xr + i;
    } else if (i < XR_F4 + WIN_F4) {
        int j = i - XR_F4; v = w_in[j]; dst = (float4*)g_win + j;
    } else if (i < XR_F4 + WIN_F4 + WOUT_F4) {
        int j = i - XR_F4 - WIN_F4; v = w_out[j]; dst = (float4*)g_wout + j;
    } else {
        int j = i - XR_F4 - WIN_F4 - WOUT_F4;
        int r = j >> 7, c = j & 127;
        int sr = (r < 512) ? r : r + 512;              // skip dead f-gate block
        v = *(const float4*)&w_ih[(size_t)sr * HDIM + c * 4];
        dst = (float4*)g_wih + j;
    }
    v.x = roundtf(v.x); v.y = roundtf(v.y); v.z = roundtf(v.z); v.w = roundtf(v.w);
    *dst = v;
}

// ---------------------------------------------------------------------------
// Pipelined GEMM: C(128 x 128) = A(128 x K) @ W(128 x K)^T.
// 3-stage cp.async ring, swizzled smem (chunk c at c^(r&7)).
// 8 warps: warp grid 2(M) x 4(N), warp tile 64 x 32 (fm4 x fn4) -> 64 acc regs,
// __launch_bounds__(256,2) caps regs at 128 -> 2 CTAs/SM (16 warps).
// ---------------------------------------------------------------------------
#define STAGE_F (2 * 128 * 32)          // floats per stage (A 128x32 + B 128x32)
#define SMEM_BYTES (3 * STAGE_F * 4)    // 96 KB

template <int K>
__device__ __forceinline__ void load_stage(
    const float* __restrict__ Aptr, const float* __restrict__ W,
    int4 ab, int n0, int tid, int k0, uint32_t aB, uint32_t bB)
{
    #pragma unroll
    for (int i = 0; i < 4; i++) {
        int idx = tid + i * 256, r = idx >> 3, c = idx & 7, p = c ^ (r & 7);
        int g = r >> 5;
        int base = (g == 0) ? ab.x : (g == 1) ? ab.y : (g == 2) ? ab.z : ab.w;
        cp16(aB + r * 128 + p * 16, Aptr + (size_t)(base + (r & 31)) * K + k0 + c * 4);
    }
    #pragma unroll
    for (int i = 0; i < 4; i++) {
        int idx = tid + i * 256, r = idx >> 3, c = idx & 7, p = c ^ (r & 7);
        cp16(bB + r * 128 + p * 16, W + (size_t)(n0 + r) * K + k0 + c * 4);
    }
    asm volatile("cp.async.commit_group;");
}

template <int MODE>
__global__ void __launch_bounds__(256, 2) k_gemm(
    const float* __restrict__ bias, float* __restrict__ Cout)
{
    constexpr int K = (MODE == 0) ? IDIM : HDIM;
    constexpr int NSLAB = K / 32;

    extern __shared__ float sm[];

    const int tid  = threadIdx.x;
    const int wid  = tid >> 5;
    const int lane = tid & 31;
    const int wm = wid >> 2;          // 0..1  (64 M-rows each)
    const int wn = wid & 3;           // 0..3  (32 N-cols each)
    const int lr = lane >> 2;         // 0..7
    const int lc = lane & 3;          // 0..3

    int s = 0;
    int aa[4] = {0, 0, 0, 0};
    int4 ab;
    const float* Aptr;
    const float* W;
    const int n0 = blockIdx.x * 128;

    if (MODE == 1) {
        int m0 = blockIdx.y * 128;
        ab = make_int4(m0, m0 + 32, m0 + 64, m0 + 96);
        Aptr = (const float*)g_xproj;
        W = (const float*)g_wih;
    } else {
        const int* t = g_sched[blockIdx.y];
        s = t[0];
        if (s < 0) return;
        int b0 = t[1];
        #pragma unroll
        for (int i = 0; i < 4; i++) aa[i] = t[1 + i];
        ab.x = ((aa[0] < 0) ? b0 : aa[0]) * 32;
        ab.y = ((aa[1] < 0) ? b0 : aa[1]) * 32;
        ab.z = ((aa[2] < 0) ? b0 : aa[2]) * 32;
        ab.w = ((aa[3] < 0) ? b0 : aa[3]) * 32;
        Aptr = (MODE == 0) ? (const float*)g_xr : (const float*)g_xproj;
        W = (MODE == 0) ? (const float*)g_win + (size_t)s * HDIM * IDIM
                        : (const float*)g_wout + (size_t)s * ODIM * HDIM;
    }

    uint32_t aB[3], bB[3];
    #pragma unroll
    for (int st = 0; st < 3; st++) {
        aB[st] = s2u(sm + st * STAGE_F);
        bB[st] = s2u(sm + st * STAGE_F + 128 * 32);
    }

    float acc[4][4][4] = {};

    load_stage<K>(Aptr, W, ab, n0, tid, 0, aB[0], bB[0]);
    load_stage<K>(Aptr, W, ab, n0, tid, 32, aB[1], bB[1]);

    for (int kt = 0; kt < NSLAB; kt++) {
        const int cur = kt % 3;
        if (kt + 1 < NSLAB) asm volatile("cp.async.wait_group 1;");
        else                asm volatile("cp.async.wait_group 0;");
        __syncthreads();

        // Prefetch kt+2 into the stage computed at kt-1 (safe: sync above
        // guarantees all warps finished compute(kt-1)).
        if (kt + 2 < NSLAB)
            load_stage<K>(Aptr, W, ab, n0, tid, (kt + 2) * 32,
                          aB[(kt + 2) % 3], bB[(kt + 2) % 3]);

        const float* At = sm + cur * STAGE_F;
        const float* Bt = sm + cur * STAGE_F + 128 * 32;

        #pragma unroll
        for (int kk = 0; kk < 4; kk++) {
            const int sw0 = ((2 * kk)     ^ lr) * 4 + lc;
            const int sw1 = ((2 * kk + 1) ^ lr) * 4 + lc;
            unsigned af[4][4];
            #pragma unroll
            for (int fm = 0; fm < 4; fm++) {
                int r0 = (wm * 64 + fm * 16 + lr) * 32;
                int r1 = r0 + 8 * 32;
                af[fm][0] = __float_as_uint(At[r0 + sw0]);
                af[fm][1] = __float_as_uint(At[r1 + sw0]);
                af[fm][2] = __float_as_uint(At[r0 + sw1]);
                af[fm][3] = __float_as_uint(At[r1 + sw1]);
            }
            unsigned bf[4][2];
            #pragma unroll
            for (int fn = 0; fn < 4; fn++) {
                int rb = (wn * 32 + fn * 8 + lr) * 32;
                bf[fn][0] = __float_as_uint(Bt[rb + sw0]);
                bf[fn][1] = __float_as_uint(Bt[rb + sw1]);
            }
            #pragma unroll
            for (int fm = 0; fm < 4; fm++)
                #pragma unroll
                for (int fn = 0; fn < 4; fn++)
                    mma_tf32(acc[fm][fn], af[fm], bf[fn]);
        }
        __syncthreads();
    }

    // Epilogue
    #pragma unroll
    for (int fm = 0; fm < 4; fm++) {
        int rl = wm * 64 + fm * 16 + lr;          // 0..127 (row, row+8 same 32-group)
        int grp = rl >> 5;
        if (MODE != 1 && aa[grp] < 0) continue;
        size_t grow0;
        if (MODE == 1) grow0 = (size_t)blockIdx.y * 128 + rl;
        else           grow0 = (size_t)aa[grp] * 32 + (rl & 31);
        size_t grow1 = grow0 + 8;

        #pragma unroll
        for (int fn = 0; fn < 4; fn++) {
            int col = n0 + wn * 32 + fn * 8 + lc * 2;
            float v00 = acc[fm][fn][0], v01 = acc[fm][fn][1];
            float v10 = acc[fm][fn][2], v11 = acc[fm][fn][3];
            if (MODE == 0) {
                float b0 = bias[s * HDIM + col], b1 = bias[s * HDIM + col + 1];
                g_xproj[grow0 * HDIM + col    ] = roundtf(fmaxf(v00 + b0, 0.0f));
                g_xproj[grow0 * HDIM + col + 1] = roundtf(fmaxf(v01 + b1, 0.0f));
                g_xproj[grow1 * HDIM + col    ] = roundtf(fmaxf(v10 + b0, 0.0f));
                g_xproj[grow1 * HDIM + col + 1] = roundtf(fmaxf(v11 + b1, 0.0f));
            } else if (MODE == 1) {
                g_gates[grow0 * NGATES + col    ] = v00;
                g_gates[grow0 * NGATES + col + 1] = v01;
                g_gates[grow1 * NGATES + col    ] = v10;
                g_gates[grow1 * NGATES + col + 1] = v11;
            } else {
                float b0 = bias[s * ODIM + col], b1 = bias[s * ODIM + col + 1];
                Cout[grow0 * ODIM + col    ] = v00 + b0;
                Cout[grow0 * ODIM + col + 1] = v01 + b1;
                Cout[grow1 * ODIM + col    ] = v10 + b0;
                Cout[grow1 * ODIM + col + 1] = v11 + b1;
            }
        }
    }
}

// ---------------------------------------------------------------------------
// Pointwise LSTM. Also writes TF32-rounded h1 into g_xproj (A of logits).
// ---------------------------------------------------------------------------
__global__ void __launch_bounds__(256) k_lstm_pw(
    const float* __restrict__ bi, const float* __restrict__ bh,
    float* __restrict__ out)
{
    int i = blockIdx.x * 256 + threadIdx.x;    // float4 index
    int row = i >> 7;
    int h = (i & 127) << 2;
    size_t g = (size_t)row * NGATES;
    float4 g1 = *(const float4*)&g_gates[g + h];
    float4 g2 = *(const float4*)&g_gates[g + 512 + h];
    float4 g3 = *(const float4*)&g_gates[g + 1024 + h];
    float4 bi1 = *(const float4*)&bi[h],        bh1 = *(const float4*)&bh[h];
    float4 bi2 = *(const float4*)&bi[1024 + h], bh2 = *(const float4*)&bh[1024 + h];
    float4 bi3 = *(const float4*)&bi[1536 + h], bh3 = *(const float4*)&bh[1536 + h];

    float4 hv, cv, hr;
    {
        float c1 = sigmoidf_(g1.x + bi1.x + bh1.x) * tanhf(g2.x + bi2.x + bh2.x);
        cv.x = c1; hv.x = sigmoidf_(g3.x + bi3.x + bh3.x) * tanhf(c1); hr.x = roundtf(hv.x);
    }
    {
        float c1 = sigmoidf_(g1.y + bi1.y + bh1.y) * tanhf(g2.y + bi2.y + bh2.y);
        cv.y = c1; hv.y = sigmoidf_(g3.y + bi3.y + bh3.y) * tanhf(c1); hr.y = roundtf(hv.y);
    }
    {
        float c1 = sigmoidf_(g1.z + bi1.z + bh1.z) * tanhf(g2.z + bi2.z + bh2.z);
        cv.z = c1; hv.z = sigmoidf_(g3.z + bi3.z + bh3.z) * tanhf(c1); hr.z = roundtf(hv.z);
    }
    {
        float c1 = sigmoidf_(g1.w + bi1.w + bh1.w) * tanhf(g2.w + bi2.w + bh2.w);
        cv.w = c1; hv.w = sigmoidf_(g3.w + bi3.w + bh3.w) * tanhf(c1); hr.w = roundtf(hv.w);
    }
    size_t o = (size_t)row * HDIM + h;
    *(float4*)&out[H_OFF + o] = hv;
    *(float4*)&out[C_OFF + o] = cv;
    *(float4*)&g_xproj[o] = hr;               // gates GEMM done; safe reuse
}

// ---------------------------------------------------------------------------
// inputs: 0 x, 1 species, 2 w_in, 3 b_in, 4 w_ih, 5 w_hh(unused), 6 b_ih,
//         7 b_hh, 8 w_out, 9 b_out
// ---------------------------------------------------------------------------
extern "C" void kernel_launch(void* const* d_in, const int* in_sizes, int n_in,
                              void* d_out, int out_size)
{
    const float* x     = (const float*)d_in[0];
    const int*   sp    = (const int*)d_in[1];
    const float* w_in  = (const float*)d_in[2];
    const float* b_in  = (const float*)d_in[3];
    const float* w_ih  = (const float*)d_in[4];
    const float* b_ih  = (const float*)d_in[6];
    const float* b_hh  = (const float*)d_in[7];
    const float* w_out = (const float*)d_in[8];
    const float* b_out = (const float*)d_in[9];
    float* out = (float*)d_out;

    static bool attr_done = false;
    if (!attr_done) {
        cudaFuncSetAttribute(k_gemm<0>, cudaFuncAttributeMaxDynamicSharedMemorySize, SMEM_BYTES);
        cudaFuncSetAttribute(k_gemm<1>, cudaFuncAttributeMaxDynamicSharedMemorySize, SMEM_BYTES);
        cudaFuncSetAttribute(k_gemm<2>, cudaFuncAttributeMaxDynamicSharedMemorySize, SMEM_BYTES);
        attr_done = true;
    }

    k_build<<<1, 512>>>(sp);

    k_round<<<(TOT_F4 + 255) / 256, 256>>>(
        (const float4*)x, (const float4*)w_in, w_ih, (const float4*)w_out);

    k_gemm<0><<<dim3(HDIM / 128, MAX_TILES), 256, SMEM_BYTES>>>(b_in, nullptr);

    k_gemm<1><<<dim3(NGATES / 128, NROWS / 128), 256, SMEM_BYTES>>>(nullptr, nullptr);

    k_lstm_pw<<<NROWS * HDIM / 4 / 256, 256>>>(b_ih, b_hh, out);

    k_gemm<2><<<dim3(ODIM / 128, MAX_TILES), 256, SMEM_BYTES>>>(b_out, out);
}

// round 8
// speedup vs baseline: 4.0640x; 1.0558x over previous
#include <cuda_runtime.h>
#include <math.h>
#include <stdint.h>

// Problem constants
#define AA 512
#define BB 32
#define IDIM 256
#define HDIM 512
#define ODIM 1024          // MSG_DIM * VOCAB
#define NROWS (AA * BB)    // 16384
#define MAX_TILES 160

// d_out layout: [logits] [h_out] [c_out]
#define LOGITS_OFF 0
#define H_OFF (AA * BB * ODIM)
#define C_OFF (H_OFF + NROWS * HDIM)

// k-dim permutation within 8-groups: logical k -> slot [0,4,1,5,2,6,3,7]^-1
// slot(k) = 2*(k%4) + k/4  (so pairs (k, k+4) are adjacent slots 2j, 2j+1)
#define KSLOT(k) ((((k) & 3) << 1) | (((k) >> 2) & 1))
__device__ __forceinline__ int kperm(int k) { return (k & ~7) | KSLOT(k & 7); }

// Scratch (pre-rounded TF32 bit patterns, k-dim permuted)
__device__ float g_xr[NROWS * IDIM];
__device__ float g_win[16 * HDIM * IDIM];
__device__ float g_wih[1536 * HDIM];       // packed row p = 3h+gate (f elided)
__device__ float g_wout[16 * ODIM * HDIM];
__device__ float g_xproj[NROWS * HDIM];    // rounded relu proj (cols permuted)
__device__ float g_h1[NROWS * HDIM];       // rounded h1 (cols permuted)
__device__ int   g_ord[AA];
__device__ int   g_sched[MAX_TILES][8];    // {species, a0..a3, pad}

__device__ __forceinline__ float sigmoidf_(float x) {
    return 1.0f / (1.0f + __expf(-x));
}
__device__ __forceinline__ unsigned f2tf32(float f) {
    unsigned r;
    asm("cvt.rna.tf32.f32 %0, %1;" : "=r"(r) : "f"(f));
    return r;
}
__device__ __forceinline__ float roundtf(float f) { return __uint_as_float(f2tf32(f)); }

__device__ __forceinline__ void mma_tf32(float* c, const unsigned* a, const unsigned* b) {
    asm volatile(
        "mma.sync.aligned.m16n8k8.row.col.f32.tf32.tf32.f32 "
        "{%0,%1,%2,%3}, {%4,%5,%6,%7}, {%8,%9}, {%0,%1,%2,%3};"
        : "+f"(c[0]), "+f"(c[1]), "+f"(c[2]), "+f"(c[3])
        : "r"(a[0]), "r"(a[1]), "r"(a[2]), "r"(a[3]), "r"(b[0]), "r"(b[1]));
}

__device__ __forceinline__ uint32_t s2u(const void* p) {
    uint32_t a;
    asm("{ .reg .u64 t; cvta.to.shared.u64 t, %1; cvt.u32.u64 %0, t; }" : "=r"(a) : "l"(p));
    return a;
}
__device__ __forceinline__ void cp16(uint32_t dst, const void* src) {
    asm volatile("cp.async.cg.shared.global [%0], [%1], 16;" :: "r"(dst), "l"(src));
}

// ---------------------------------------------------------------------------
// Schedule builder: species-bucketed 128-row tiles.
// ---------------------------------------------------------------------------
__global__ void k_build(const int* __restrict__ sp) {
    __shared__ int cnt[16], base[16], off[16], tb[17];
    int t = threadIdx.x;
    if (t < 16) cnt[t] = 0;
    __syncthreads();
    if (t < AA) atomicAdd(&cnt[sp[t]], 1);
    __syncthreads();
    if (t == 0) {
        int a = 0, tc = 0;
        for (int q = 0; q < 16; q++) {
            base[q] = a; off[q] = a; a += cnt[q];
            tb[q] = tc; tc += (cnt[q] + 3) >> 2;
        }
        tb[16] = tc;
    }
    __syncthreads();
    if (t < AA) {
        int s = sp[t];
        int slot = atomicAdd(&off[s], 1);
        g_ord[slot] = t;
    }
    __syncthreads();
    if (t < MAX_TILES) {
        int s = -1;
        for (int q = 0; q < 16; q++)
            if (t >= tb[q] && t < tb[q + 1]) s = q;
        g_sched[t][0] = s;
        if (s >= 0) {
            int ti = t - tb[s];
            #pragma unroll
            for (int j = 0; j < 4; j++) {
                int idx = ti * 4 + j;
                g_sched[t][1 + j] = (idx < cnt[s]) ? g_ord[base[s] + idx] : -1;
            }
        }
    }
}

// ---------------------------------------------------------------------------
// Pre-round + k-permute x, w_in, w_out, interleave-packed w_ih.
// Each thread handles 4 consecutive logical-k elements (4-aligned), which
// scatter to slots grp+hf+{0,2,4,6}.
// ---------------------------------------------------------------------------
#define XR_F4   (NROWS * IDIM / 4)
#define WIN_F4  (16 * HDIM * IDIM / 4)
#define WOUT_F4 (16 * ODIM * HDIM / 4)
#define WIH_F4  (1536 * HDIM / 4)
#define TOT_F4  (XR_F4 + WIN_F4 + WOUT_F4 + WIH_F4)

__global__ void __launch_bounds__(256) k_round(
    const float4* __restrict__ x, const float4* __restrict__ w_in,
    const float* __restrict__ w_ih, const float4* __restrict__ w_out)
{
    int i = blockIdx.x * 256 + threadIdx.x;
    if (i >= TOT_F4) return;
    float4 v; float* dst; int e0;
    if (i < XR_F4) {
        v = x[i]; dst = g_xr; e0 = i * 4;
    } else if (i < XR_F4 + WIN_F4) {
        int j = i - XR_F4; v = w_in[j]; dst = g_win; e0 = j * 4;
    } else if (i < XR_F4 + WIN_F4 + WOUT_F4) {
        int j = i - XR_F4 - WIN_F4; v = w_out[j]; dst = g_wout; e0 = j * 4;
    } else {
        int j = i - XR_F4 - WIN_F4 - WOUT_F4;
        int p = j >> 7, c = j & 127;               // packed row p = 3h+gate
        int h = p / 3, gate = p - 3 * h;
        int sr = (gate == 0) ? h : (gate == 1) ? 1024 + h : 1536 + h;
        v = *(const float4*)&w_ih[(size_t)sr * HDIM + c * 4];
        dst = g_wih; e0 = j * 4;
    }
    int grp = e0 & ~7;
    int hf  = (e0 >> 2) & 1;
    dst[grp + hf    ] = roundtf(v.x);
    dst[grp + hf + 2] = roundtf(v.y);
    dst[grp + hf + 4] = roundtf(v.z);
    dst[grp + hf + 6] = roundtf(v.w);
}

// ---------------------------------------------------------------------------
// Pipelined TF32 mma GEMM. SMEM rows = 160B stride (8 chunks used + 2 pad)
// so permuted uint2 fragment loads are bank-conflict-free.
// 8 warps: warp grid 2(M) x 4(N). 2-stage cp.async, 1 barrier per 32-k slab.
// MODE 0: xproj  BN=128 (warp 64x32), K=256: relu+bias, round, perm-col -> g_xproj
// MODE 1: gates  BN=96  (warp 64x24), K=512: interleaved i/g/o; fused LSTM ->
//                h_out/c_out + rounded perm-col h1 -> g_h1
// MODE 2: logits BN=128 (warp 64x32), K=512: bias -> out
// ---------------------------------------------------------------------------
#define ROWB 160                                   // bytes per smem row

template <int MODE>
__global__ void __launch_bounds__(256, 2) k_gemm(
    const float* __restrict__ bias1, const float* __restrict__ bias2,
    float* __restrict__ Cout)
{
    constexpr int K = (MODE == 0) ? IDIM : HDIM;
    constexpr int NSLAB = K / 32;
    constexpr int BN = (MODE == 1) ? 96 : 128;
    constexpr int FN = (MODE == 1) ? 3 : 4;
    constexpr int WN = FN * 8;                     // warp N width
    constexpr int ABYTES = 128 * ROWB;             // 20 KB
    constexpr int BBYTES = BN * ROWB;
    constexpr int STAGEB = ABYTES + BBYTES;

    extern __shared__ char smraw[];
    const uint32_t smbase = s2u(smraw);

    const int tid  = threadIdx.x;
    const int wid  = tid >> 5;
    const int lane = tid & 31;
    const int wm = wid >> 2;          // 0..1
    const int wn = wid & 3;           // 0..3
    const int lr = lane >> 2;         // 0..7
    const int lc = lane & 3;          // 0..3
    const int n0 = blockIdx.x * BN;

    int s = 0, m0 = 0;
    int aa[4] = {0, 0, 0, 0};
    int ab[4];
    const float* Aptr;
    const float* W;

    if (MODE == 1) {
        m0 = blockIdx.y * 128;
        ab[0] = m0; ab[1] = m0 + 32; ab[2] = m0 + 64; ab[3] = m0 + 96;
        Aptr = g_xproj;
        W = g_wih;
    } else {
        const int* t = g_sched[blockIdx.y];
        s = t[0];
        if (s < 0) return;
        int b0 = t[1];
        #pragma unroll
        for (int i = 0; i < 4; i++) {
            aa[i] = t[1 + i];
            ab[i] = ((aa[i] < 0) ? b0 : aa[i]) * 32;   // clamp pads (loads only)
        }
        Aptr = (MODE == 0) ? g_xr : g_h1;
        W = (MODE == 0) ? g_win + (size_t)s * HDIM * IDIM
                        : g_wout + (size_t)s * ODIM * HDIM;
    }

    auto load_slab = [&](int kt) {
        const int k0 = kt * 32;
        const uint32_t stb = smbase + (kt & 1) * STAGEB;
        #pragma unroll
        for (int i = 0; i < 4; i++) {              // A: 128 rows x 8 chunks
            int idx = tid + i * 256, r = idx >> 3, c = idx & 7;
            cp16(stb + r * ROWB + c * 16,
                 Aptr + (size_t)(ab[r >> 5] + (r & 31)) * K + k0 + c * 4);
        }
        #pragma unroll
        for (int i = 0; i < BN / 32; i++) {        // B: BN rows x 8 chunks
            int idx = tid + i * 256, r = idx >> 3, c = idx & 7;
            cp16(stb + ABYTES + r * ROWB + c * 16,
                 W + (size_t)(n0 + r) * K + k0 + c * 4);
        }
        asm volatile("cp.async.commit_group;");
    };

    float acc[4][FN][4];
    #pragma unroll
    for (int a = 0; a < 4; a++)
        #pragma unroll
        for (int b = 0; b < FN; b++)
            #pragma unroll
            for (int c = 0; c < 4; c++) acc[a][b][c] = 0.0f;

    load_slab(0);

    for (int kt = 0; kt < NSLAB; kt++) {
        asm volatile("cp.async.wait_group 0;");
        __syncthreads();                           // data ready; prev compute done
        if (kt + 1 < NSLAB) load_slab(kt + 1);     // overlaps with compute below

        const char* At = smraw + (kt & 1) * STAGEB;
        const char* Bt = At + ABYTES;

        #pragma unroll
        for (int kk = 0; kk < 4; kk++) {
            const int kb = kk * 32 + lc * 8;       // permuted uint2 byte offset
            uint2 av[4][2];
            #pragma unroll
            for (int fm = 0; fm < 4; fm++) {
                int r0 = wm * 64 + fm * 16 + lr;
                av[fm][0] = *(const uint2*)(At + r0 * ROWB + kb);
                av[fm][1] = *(const uint2*)(At + (r0 + 8) * ROWB + kb);
            }
            uint2 bv[FN];
            #pragma unroll
            for (int fn = 0; fn < FN; fn++)
                bv[fn] = *(const uint2*)(Bt + (wn * WN + fn * 8 + lr) * ROWB + kb);
            #pragma unroll
            for (int fm = 0; fm < 4; fm++) {
                unsigned af[4] = { av[fm][0].x, av[fm][1].x, av[fm][0].y, av[fm][1].y };
                #pragma unroll
                for (int fn = 0; fn < FN; fn++) {
                    unsigned bf[2] = { bv[fn].x, bv[fn].y };
                    mma_tf32(acc[fm][fn], af, bf);
                }
            }
        }
    }

    // ------------------------------ Epilogue -------------------------------
    if (MODE == 1) {
        // Fused LSTM. Warp-local exchange through smem (reuse stages).
        __syncthreads();                           // all warps done with stages
        float* scr = (float*)smraw + wid * (64 * 25);   // 64 rows x 24 cols pad 25
        #pragma unroll
        for (int fm = 0; fm < 4; fm++) {
            int rr0 = fm * 16 + lr;
            #pragma unroll
            for (int fn = 0; fn < FN; fn++) {
                int cc = fn * 8 + lc * 2;
                scr[rr0 * 25 + cc]            = acc[fm][fn][0];
                scr[rr0 * 25 + cc + 1]        = acc[fm][fn][1];
                scr[(rr0 + 8) * 25 + cc]      = acc[fm][fn][2];
                scr[(rr0 + 8) * 25 + cc + 1]  = acc[fm][fn][3];
            }
        }
        __syncwarp();
        const int hb = (n0 + wn * WN) / 3;         // 8 h per warp window
        const int rowb = m0 + wm * 64;
        #pragma unroll
        for (int it = 0; it < 16; it++) {
            int item = it * 32 + lane;             // 64 rows x 8 h
            int rr = item >> 3, hh = item & 7;
            int h = hb + hh;
            float gi = scr[rr * 25 + hh * 3    ] + bias1[h]        + bias2[h];
            float gg = scr[rr * 25 + hh * 3 + 1] + bias1[1024 + h] + bias2[1024 + h];
            float go = scr[rr * 25 + hh * 3 + 2] + bias1[1536 + h] + bias2[1536 + h];
            float c1 = sigmoidf_(gi) * tanhf(gg);  // f*c0 == 0
            float h1 = sigmoidf_(go) * tanhf(c1);
            size_t row = (size_t)(rowb + rr);
            Cout[H_OFF + row * HDIM + h] = h1;
            Cout[C_OFF + row * HDIM + h] = c1;
            g_h1[row * HDIM + kperm(h)] = roundtf(h1);
        }
    } else {
        #pragma unroll
        for (int fm = 0; fm < 4; fm++) {
            int rl = wm * 64 + fm * 16 + lr;
            int grp = rl >> 5;
            if (aa[grp] < 0) continue;
            size_t grow0 = (size_t)aa[grp] * 32 + (rl & 31);
            size_t grow1 = grow0 + 8;
            #pragma unroll
            for (int fn = 0; fn < FN; fn++) {
                int col = n0 + wn * WN + fn * 8 + lc * 2;
                float v00 = acc[fm][fn][0], v01 = acc[fm][fn][1];
                float v10 = acc[fm][fn][2], v11 = acc[fm][fn][3];
                if (MODE == 0) {
                    float b0 = bias1[s * HDIM + col], b1 = bias1[s * HDIM + col + 1];
                    int p0 = kperm(col), p1 = kperm(col + 1);
                    g_xproj[grow0 * HDIM + p0] = roundtf(fmaxf(v00 + b0, 0.0f));
                    g_xproj[grow0 * HDIM + p1] = roundtf(fmaxf(v01 + b1, 0.0f));
                    g_xproj[grow1 * HDIM + p0] = roundtf(fmaxf(v10 + b0, 0.0f));
                    g_xproj[grow1 * HDIM + p1] = roundtf(fmaxf(v11 + b1, 0.0f));
                } else {
                    float b0 = bias1[s * ODIM + col], b1 = bias1[s * ODIM + col + 1];
                    Cout[grow0 * ODIM + col    ] = v00 + b0;
                    Cout[grow0 * ODIM + col + 1] = v01 + b1;
                    Cout[grow1 * ODIM + col    ] = v10 + b0;
                    Cout[grow1 * ODIM + col + 1] = v11 + b1;
                }
            }
        }
    }
}

// ---------------------------------------------------------------------------
// inputs: 0 x, 1 species, 2 w_in, 3 b_in, 4 w_ih, 5 w_hh(unused), 6 b_ih,
//         7 b_hh, 8 w_out, 9 b_out
// ---------------------------------------------------------------------------
extern "C" void kernel_launch(void* const* d_in, const int* in_sizes, int n_in,
                              void* d_out, int out_size)
{
    const float* x     = (const float*)d_in[0];
    const int*   sp    = (const int*)d_in[1];
    const float* w_in  = (const float*)d_in[2];
    const float* b_in  = (const float*)d_in[3];
    const float* w_ih  = (const float*)d_in[4];
    const float* b_ih  = (const float*)d_in[6];
    const float* b_hh  = (const float*)d_in[7];
    const float* w_out = (const float*)d_in[8];
    const float* b_out = (const float*)d_in[9];
    float* out = (float*)d_out;

    const int SMEM02 = 2 * (128 * ROWB + 128 * ROWB);   // 80 KB
    const int SMEM1  = 2 * (128 * ROWB + 96 * ROWB);    // 70 KB

    static bool attr_done = false;
    if (!attr_done) {
        cudaFuncSetAttribute(k_gemm<0>, cudaFuncAttributeMaxDynamicSharedMemorySize, SMEM02);
        cudaFuncSetAttribute(k_gemm<1>, cudaFuncAttributeMaxDynamicSharedMemorySize, SMEM1);
        cudaFuncSetAttribute(k_gemm<2>, cudaFuncAttributeMaxDynamicSharedMemorySize, SMEM02);
        attr_done = true;
    }

    k_build<<<1, 512>>>(sp);

    k_round<<<(TOT_F4 + 255) / 256, 256>>>(
        (const float4*)x, (const float4*)w_in, w_ih, (const float4*)w_out);

    // xproj: N=512 -> 4 tiles of 128, species-scheduled M tiles
    k_gemm<0><<<dim3(4, MAX_TILES), 256, SMEM02>>>(b_in, nullptr, nullptr);

    // gates (interleaved 3h+gate, fused LSTM): N=1536 -> 16 tiles of 96
    k_gemm<1><<<dim3(16, NROWS / 128), 256, SMEM1>>>(b_ih, b_hh, out);

    // logits: N=1024 -> 8 tiles of 128, species-scheduled M tiles
    k_gemm<2><<<dim3(8, MAX_TILES), 256, SMEM02>>>(b_out, nullptr, out);
}

// round 9
// speedup vs baseline: 5.3877x; 1.3257x over previous
#include <cuda_runtime.h>
#include <cuda_fp16.h>
#include <math.h>
#include <stdint.h>

// Problem constants
#define AA 512
#define BB 32
#define IDIM 256
#define HDIM 512
#define ODIM 1024          // MSG_DIM * VOCAB
#define NROWS (AA * BB)    // 16384
#define MAX_TILES 160

// d_out layout: [logits] [h_out] [c_out]
#define LOGITS_OFF 0
#define H_OFF (AA * BB * ODIM)
#define C_OFF (H_OFF + NROWS * HDIM)

// 16-group k permutation: pair p (k=2p,2p+1) -> slot-pair 2*(p%4)+p/4, so the
// fp16 m16n8k16 fragment halves (2lc,2lc+1,2lc+8,2lc+9) form one 8B word.
__device__ __forceinline__ int perm16(int k) {
    int g = k & ~15, j = k & 15, p = j >> 1, o = j & 1;
    return g + (((((p & 3) << 1) | (p >> 2))) << 1) + o;
}

// Scratch (fp16, k-dim permuted)
__device__ __half g_xr[NROWS * IDIM];
__device__ __half g_win[16 * HDIM * IDIM];
__device__ __half g_wih[1536 * HDIM];      // packed row p = 3h+gate (f elided)
__device__ __half g_wout[16 * ODIM * HDIM];
__device__ __half g_xproj[NROWS * HDIM];   // relu proj (cols permuted)
__device__ __half g_h1[NROWS * HDIM];      // h1 (cols permuted)
__device__ int    g_ord[AA];
__device__ int    g_sched[MAX_TILES][8];   // {species, a0..a3, pad}

__device__ __forceinline__ float sigmoidf_(float x) {
    return 1.0f / (1.0f + __expf(-x));
}

__device__ __forceinline__ void mma_f16(float* c, const unsigned* a, const unsigned* b) {
    asm volatile(
        "mma.sync.aligned.m16n8k16.row.col.f32.f16.f16.f32 "
        "{%0,%1,%2,%3}, {%4,%5,%6,%7}, {%8,%9}, {%0,%1,%2,%3};"
        : "+f"(c[0]), "+f"(c[1]), "+f"(c[2]), "+f"(c[3])
        : "r"(a[0]), "r"(a[1]), "r"(a[2]), "r"(a[3]), "r"(b[0]), "r"(b[1]));
}

__device__ __forceinline__ uint32_t s2u(const void* p) {
    uint32_t a;
    asm("{ .reg .u64 t; cvta.to.shared.u64 t, %1; cvt.u32.u64 %0, t; }" : "=r"(a) : "l"(p));
    return a;
}
__device__ __forceinline__ void cp16(uint32_t dst, const void* src) {
    asm volatile("cp.async.cg.shared.global [%0], [%1], 16;" :: "r"(dst), "l"(src));
}

// ---------------------------------------------------------------------------
// Schedule builder: species-bucketed 128-row tiles.
// ---------------------------------------------------------------------------
__global__ void k_build(const int* __restrict__ sp) {
    __shared__ int cnt[16], base[16], off[16], tb[17];
    int t = threadIdx.x;
    if (t < 16) cnt[t] = 0;
    __syncthreads();
    if (t < AA) atomicAdd(&cnt[sp[t]], 1);
    __syncthreads();
    if (t == 0) {
        int a = 0, tc = 0;
        for (int q = 0; q < 16; q++) {
            base[q] = a; off[q] = a; a += cnt[q];
            tb[q] = tc; tc += (cnt[q] + 3) >> 2;
        }
        tb[16] = tc;
    }
    __syncthreads();
    if (t < AA) {
        int s = sp[t];
        int slot = atomicAdd(&off[s], 1);
        g_ord[slot] = t;
    }
    __syncthreads();
    if (t < MAX_TILES) {
        int s = -1;
        for (int q = 0; q < 16; q++)
            if (t >= tb[q] && t < tb[q + 1]) s = q;
        g_sched[t][0] = s;
        if (s >= 0) {
            int ti = t - tb[s];
            #pragma unroll
            for (int j = 0; j < 4; j++) {
                int idx = ti * 4 + j;
                g_sched[t][1 + j] = (idx < cnt[s]) ? g_ord[base[s] + idx] : -1;
            }
        }
    }
}

// ---------------------------------------------------------------------------
// Convert + k-permute x, w_in, w_out, interleave-packed w_ih to fp16.
// Each thread handles 8 consecutive k (8-aligned, never crosses a row).
// ---------------------------------------------------------------------------
#define XR_E   (NROWS * IDIM)
#define WIN_E  (16 * HDIM * IDIM)
#define WOUT_E (16 * ODIM * HDIM)
#define WIH_E  (1536 * HDIM)
#define TOT_T  ((XR_E + WIN_E + WOUT_E + WIH_E) / 8)

__global__ void __launch_bounds__(256) k_cvt(
    const float4* __restrict__ x, const float4* __restrict__ w_in,
    const float* __restrict__ w_ih, const float4* __restrict__ w_out)
{
    int i = blockIdx.x * 256 + threadIdx.x;
    if (i >= TOT_T) return;
    float4 v0, v1; __half* dst; int e0;
    if (i < XR_E / 8) {
        e0 = i * 8; v0 = x[i*2]; v1 = x[i*2+1]; dst = g_xr;
    } else if (i < (XR_E + WIN_E) / 8) {
        int j = i - XR_E / 8; e0 = j * 8;
        v0 = w_in[j*2]; v1 = w_in[j*2+1]; dst = g_win;
    } else if (i < (XR_E + WIN_E + WOUT_E) / 8) {
        int j = i - (XR_E + WIN_E) / 8; e0 = j * 8;
        v0 = w_out[j*2]; v1 = w_out[j*2+1]; dst = g_wout;
    } else {
        int j = i - (XR_E + WIN_E + WOUT_E) / 8; e0 = j * 8;
        int p = e0 >> 9, c = e0 & 511;             // packed row p = 3h+gate
        int h = p / 3, gate = p - 3 * h;
        int sr = (gate == 0) ? h : (gate == 1) ? 1024 + h : 1536 + h;
        const float4* src = (const float4*)&w_ih[(size_t)sr * HDIM + c];
        v0 = src[0]; v1 = src[1]; dst = g_wih;
    }
    float vv[8] = { v0.x, v0.y, v0.z, v0.w, v1.x, v1.y, v1.z, v1.w };
    int g = e0 & ~15;
    int hi = (e0 >> 3) & 1;                        // which half of the 16-group
    __half2* d2 = (__half2*)dst;
    #pragma unroll
    for (int t = 0; t < 4; t++) {
        int sp = t * 2 + hi;                       // slot-pair
        d2[((g >> 1) + sp)] = __floats2half2_rn(vv[t*2], vv[t*2+1]);
    }
}

// ---------------------------------------------------------------------------
// Pipelined fp16 m16n8k16 GEMM. K-slab = 64 halves (128B rows + 16B pad).
// 8 warps: warp grid 2(M) x 4(N). 2-stage cp.async, 1 barrier per slab.
// MODE 0: xproj  BN=128 (warp 64x32), K=256: relu+bias -> g_xproj (fp16 perm)
// MODE 1: gates  BN=96  (warp 64x24), K=512: interleaved i/g/o; fused LSTM ->
//                h_out/c_out (fp32) + h1 -> g_h1 (fp16 perm)
// MODE 2: logits BN=128 (warp 64x32), K=512: bias -> out (fp32)
// ---------------------------------------------------------------------------
#define ROWB 144                                   // 128B data + 16B pad

template <int MODE>
__global__ void __launch_bounds__(256, 2) k_gemm(
    const float* __restrict__ bias1, const float* __restrict__ bias2,
    float* __restrict__ Cout)
{
    constexpr int K = (MODE == 0) ? IDIM : HDIM;   // halves
    constexpr int NSLAB = K / 64;
    constexpr int BN = (MODE == 1) ? 96 : 128;
    constexpr int FN = (MODE == 1) ? 3 : 4;
    constexpr int WN = FN * 8;
    constexpr int ABYTES = 128 * ROWB;             // 18 KB
    constexpr int BBYTES = BN * ROWB;
    constexpr int STAGEB = ABYTES + BBYTES;

    extern __shared__ char smraw[];
    const uint32_t smbase = s2u(smraw);

    const int tid  = threadIdx.x;
    const int wid  = tid >> 5;
    const int lane = tid & 31;
    const int wm = wid >> 2;          // 0..1
    const int wn = wid & 3;           // 0..3
    const int lr = lane >> 2;         // 0..7
    const int lc = lane & 3;          // 0..3
    const int n0 = blockIdx.x * BN;

    int s = 0, m0 = 0;
    int aa[4] = {0, 0, 0, 0};
    int ab[4];
    const __half* Aptr;
    const __half* W;

    if (MODE == 1) {
        m0 = blockIdx.y * 128;
        ab[0] = m0; ab[1] = m0 + 32; ab[2] = m0 + 64; ab[3] = m0 + 96;
        Aptr = g_xproj;
        W = g_wih;
    } else {
        const int* t = g_sched[blockIdx.y];
        s = t[0];
        if (s < 0) return;
        int b0 = t[1];
        #pragma unroll
        for (int i = 0; i < 4; i++) {
            aa[i] = t[1 + i];
            ab[i] = ((aa[i] < 0) ? b0 : aa[i]) * 32;   // clamp pads (loads only)
        }
        Aptr = (MODE == 0) ? g_xr : g_h1;
        W = (MODE == 0) ? g_win + (size_t)s * HDIM * IDIM
                        : g_wout + (size_t)s * ODIM * HDIM;
    }

    auto load_slab = [&](int kt) {
        const int k0 = kt * 64;
        const uint32_t stb = smbase + (kt & 1) * STAGEB;
        #pragma unroll
        for (int i = 0; i < 4; i++) {              // A: 128 rows x 8 chunks (8 halves)
            int idx = tid + i * 256, r = idx >> 3, c = idx & 7;
            cp16(stb + r * ROWB + c * 16,
                 Aptr + (size_t)(ab[r >> 5] + (r & 31)) * K + k0 + c * 8);
        }
        #pragma unroll
        for (int i = 0; i < BN / 32; i++) {        // B: BN rows x 8 chunks
            int idx = tid + i * 256, r = idx >> 3, c = idx & 7;
            cp16(stb + ABYTES + r * ROWB + c * 16,
                 W + (size_t)(n0 + r) * K + k0 + c * 8);
        }
        asm volatile("cp.async.commit_group;");
    };

    // Hoisted smem row offsets (constant across slabs)
    int aoff0[4], boff0[FN];
    #pragma unroll
    for (int fm = 0; fm < 4; fm++)
        aoff0[fm] = (wm * 64 + fm * 16 + lr) * ROWB + lc * 8;
    #pragma unroll
    for (int fn = 0; fn < FN; fn++)
        boff0[fn] = ABYTES + (wn * WN + fn * 8 + lr) * ROWB + lc * 8;

    float acc[4][FN][4];
    #pragma unroll
    for (int a = 0; a < 4; a++)
        #pragma unroll
        for (int b = 0; b < FN; b++)
            #pragma unroll
            for (int c = 0; c < 4; c++) acc[a][b][c] = 0.0f;

    load_slab(0);

    for (int kt = 0; kt < NSLAB; kt++) {
        asm volatile("cp.async.wait_group 0;");
        __syncthreads();                           // data ready; prev compute done
        if (kt + 1 < NSLAB) load_slab(kt + 1);     // overlaps with compute below

        const char* St = smraw + (kt & 1) * STAGEB;

        #pragma unroll
        for (int kk = 0; kk < 4; kk++) {           // 16 k per kk
            const int kb = kk * 32;
            uint2 av[4][2];
            #pragma unroll
            for (int fm = 0; fm < 4; fm++) {
                av[fm][0] = *(const uint2*)(St + aoff0[fm] + kb);
                av[fm][1] = *(const uint2*)(St + aoff0[fm] + 8 * ROWB + kb);
            }
            uint2 bv[FN];
            #pragma unroll
            for (int fn = 0; fn < FN; fn++)
                bv[fn] = *(const uint2*)(St + boff0[fn] + kb);
            #pragma unroll
            for (int fm = 0; fm < 4; fm++) {
                unsigned af[4] = { av[fm][0].x, av[fm][1].x, av[fm][0].y, av[fm][1].y };
                #pragma unroll
                for (int fn = 0; fn < FN; fn++) {
                    unsigned bf[2] = { bv[fn].x, bv[fn].y };
                    mma_f16(acc[fm][fn], af, bf);
                }
            }
        }
    }

    // ------------------------------ Epilogue -------------------------------
    if (MODE == 1) {
        __syncthreads();                           // stages free for scratch
        float* scr = (float*)smraw + wid * (64 * 25);   // 64 rows x 24 cols pad 25
        #pragma unroll
        for (int fm = 0; fm < 4; fm++) {
            int rr0 = fm * 16 + lr;
            #pragma unroll
            for (int fn = 0; fn < FN; fn++) {
                int cc = fn * 8 + lc * 2;
                scr[rr0 * 25 + cc]            = acc[fm][fn][0];
                scr[rr0 * 25 + cc + 1]        = acc[fm][fn][1];
                scr[(rr0 + 8) * 25 + cc]      = acc[fm][fn][2];
                scr[(rr0 + 8) * 25 + cc + 1]  = acc[fm][fn][3];
            }
        }
        __syncwarp();
        const int hb = (n0 + wn * WN) / 3;         // 8 h per warp window
        const int rowb = m0 + wm * 64;
        #pragma unroll
        for (int it = 0; it < 16; it++) {
            int item = it * 32 + lane;             // 64 rows x 8 h
            int rr = item >> 3, hh = item & 7;
            int h = hb + hh;
            float gi = scr[rr * 25 + hh * 3    ] + bias1[h]        + bias2[h];
            float gg = scr[rr * 25 + hh * 3 + 1] + bias1[1024 + h] + bias2[1024 + h];
            float go = scr[rr * 25 + hh * 3 + 2] + bias1[1536 + h] + bias2[1536 + h];
            float c1 = sigmoidf_(gi) * tanhf(gg);  // f*c0 == 0
            float h1 = sigmoidf_(go) * tanhf(c1);
            size_t row = (size_t)(rowb + rr);
            Cout[H_OFF + row * HDIM + h] = h1;
            Cout[C_OFF + row * HDIM + h] = c1;
            g_h1[row * HDIM + perm16(h)] = __float2half(h1);
        }
    } else {
        #pragma unroll
        for (int fm = 0; fm < 4; fm++) {
            int rl = wm * 64 + fm * 16 + lr;
            int grp = rl >> 5;
            if (aa[grp] < 0) continue;
            size_t grow0 = (size_t)aa[grp] * 32 + (rl & 31);
            size_t grow1 = grow0 + 8;
            #pragma unroll
            for (int fn = 0; fn < FN; fn++) {
                int col = n0 + wn * WN + fn * 8 + lc * 2;
                float v00 = acc[fm][fn][0], v01 = acc[fm][fn][1];
                float v10 = acc[fm][fn][2], v11 = acc[fm][fn][3];
                if (MODE == 0) {
                    float b0 = bias1[s * HDIM + col], b1 = bias1[s * HDIM + col + 1];
                    int p0 = perm16(col);          // even; perm16(col+1) = p0+1
                    *(__half2*)&g_xproj[grow0 * HDIM + p0] =
                        __floats2half2_rn(fmaxf(v00 + b0, 0.0f), fmaxf(v01 + b1, 0.0f));
                    *(__half2*)&g_xproj[grow1 * HDIM + p0] =
                        __floats2half2_rn(fmaxf(v10 + b0, 0.0f), fmaxf(v11 + b1, 0.0f));
                } else {
                    float b0 = bias1[s * ODIM + col], b1 = bias1[s * ODIM + col + 1];
                    Cout[grow0 * ODIM + col    ] = v00 + b0;
                    Cout[grow0 * ODIM + col + 1] = v01 + b1;
                    Cout[grow1 * ODIM + col    ] = v10 + b0;
                    Cout[grow1 * ODIM + col + 1] = v11 + b1;
                }
            }
        }
    }
}

// ---------------------------------------------------------------------------
// inputs: 0 x, 1 species, 2 w_in, 3 b_in, 4 w_ih, 5 w_hh(unused), 6 b_ih,
//         7 b_hh, 8 w_out, 9 b_out
// ---------------------------------------------------------------------------
extern "C" void kernel_launch(void* const* d_in, const int* in_sizes, int n_in,
                              void* d_out, int out_size)
{
    const float* x     = (const float*)d_in[0];
    const int*   sp    = (const int*)d_in[1];
    const float* w_in  = (const float*)d_in[2];
    const float* b_in  = (const float*)d_in[3];
    const float* w_ih  = (const float*)d_in[4];
    const float* b_ih  = (const float*)d_in[6];
    const float* b_hh  = (const float*)d_in[7];
    const float* w_out = (const float*)d_in[8];
    const float* b_out = (const float*)d_in[9];
    float* out = (float*)d_out;

    const int SMEM02 = 2 * (128 * ROWB + 128 * ROWB);   // 72 KB
    const int SMEM1  = 2 * (128 * ROWB + 96 * ROWB);    // 63 KB

    static bool attr_done = false;
    if (!attr_done) {
        cudaFuncSetAttribute(k_gemm<0>, cudaFuncAttributeMaxDynamicSharedMemorySize, SMEM02);
        cudaFuncSetAttribute(k_gemm<1>, cudaFuncAttributeMaxDynamicSharedMemorySize, SMEM1);
        cudaFuncSetAttribute(k_gemm<2>, cudaFuncAttributeMaxDynamicSharedMemorySize, SMEM02);
        attr_done = true;
    }

    k_build<<<1, 512>>>(sp);

    k_cvt<<<(TOT_T + 255) / 256, 256>>>(
        (const float4*)x, (const float4*)w_in, w_ih, (const float4*)w_out);

    // xproj: N=512 -> 4 tiles of 128, species-scheduled M tiles
    k_gemm<0><<<dim3(4, MAX_TILES), 256, SMEM02>>>(b_in, nullptr, nullptr);

    // gates (interleaved 3h+gate, fused LSTM): N=1536 -> 16 tiles of 96
    k_gemm<1><<<dim3(16, NROWS / 128), 256, SMEM1>>>(b_ih, b_hh, out);

    // logits: N=1024 -> 8 tiles of 128, species-scheduled M tiles
    k_gemm<2><<<dim3(8, MAX_TILES), 256, SMEM02>>>(b_out, nullptr, out);
}

// round 11
// speedup vs baseline: 7.1104x; 1.3197x over previous
#include <cuda_runtime.h>
#include <cuda_fp16.h>
#include <math.h>
#include <stdint.h>

// Problem constants
#define AA 512
#define BB 32
#define IDIM 256
#define HDIM 512
#define ODIM 1024          // MSG_DIM * VOCAB
#define NROWS (AA * BB)    // 16384
#define MAX_TILES 160

// d_out layout: [logits] [h_out] [c_out]
#define LOGITS_OFF 0
#define H_OFF (AA * BB * ODIM)
#define C_OFF (H_OFF + NROWS * HDIM)

// Scratch (fp16, natural k order)
__device__ __half g_xr[NROWS * IDIM];
__device__ __half g_win[16 * HDIM * IDIM];
__device__ __half g_wih[1536 * HDIM];      // packed row p = 3h+gate (f elided)
__device__ __half g_wout[16 * ODIM * HDIM];
__device__ __half g_xproj[NROWS * HDIM];   // relu projection
__device__ __half g_h1[NROWS * HDIM];      // h1
__device__ int    g_ord[AA];
__device__ int    g_sched[MAX_TILES][8];   // {species, a0..a3, pad}

__device__ __forceinline__ float sigmoidf_(float x) {
    return 1.0f / (1.0f + __expf(-x));
}

__device__ __forceinline__ void mma_f16(float* c, const unsigned* a, const unsigned* b) {
    asm volatile(
        "mma.sync.aligned.m16n8k16.row.col.f32.f16.f16.f32 "
        "{%0,%1,%2,%3}, {%4,%5,%6,%7}, {%8,%9}, {%0,%1,%2,%3};"
        : "+f"(c[0]), "+f"(c[1]), "+f"(c[2]), "+f"(c[3])
        : "r"(a[0]), "r"(a[1]), "r"(a[2]), "r"(a[3]), "r"(b[0]), "r"(b[1]));
}

__device__ __forceinline__ void ldsm_x4(unsigned* r, uint32_t addr) {
    asm volatile("ldmatrix.sync.aligned.m8n8.x4.shared.b16 {%0,%1,%2,%3}, [%4];"
                 : "=r"(r[0]), "=r"(r[1]), "=r"(r[2]), "=r"(r[3]) : "r"(addr));
}
__device__ __forceinline__ void ldsm_x2(unsigned* r, uint32_t addr) {
    asm volatile("ldmatrix.sync.aligned.m8n8.x2.shared.b16 {%0,%1}, [%2];"
                 : "=r"(r[0]), "=r"(r[1]) : "r"(addr));
}

__device__ __forceinline__ uint32_t s2u(const void* p) {
    uint32_t a;
    asm("{ .reg .u64 t; cvta.to.shared.u64 t, %1; cvt.u32.u64 %0, t; }" : "=r"(a) : "l"(p));
    return a;
}
__device__ __forceinline__ void cp16(uint32_t dst, const void* src) {
    asm volatile("cp.async.cg.shared.global [%0], [%1], 16;" :: "r"(dst), "l"(src));
}

// ---------------------------------------------------------------------------
// Schedule builder: species-bucketed 128-row tiles.
// ---------------------------------------------------------------------------
__global__ void k_build(const int* __restrict__ sp) {
    __shared__ int cnt[16], base[16], off[16], tb[17];
    int t = threadIdx.x;
    if (t < 16) cnt[t] = 0;
    __syncthreads();
    if (t < AA) atomicAdd(&cnt[sp[t]], 1);
    __syncthreads();
    if (t == 0) {
        int a = 0, tc = 0;
        for (int q = 0; q < 16; q++) {
            base[q] = a; off[q] = a; a += cnt[q];
            tb[q] = tc; tc += (cnt[q] + 3) >> 2;
        }
        tb[16] = tc;
    }
    __syncthreads();
    if (t < AA) {
        int s = sp[t];
        int slot = atomicAdd(&off[s], 1);
        g_ord[slot] = t;
    }
    __syncthreads();
    if (t < MAX_TILES) {
        int s = -1;
        for (int q = 0; q < 16; q++)
            if (t >= tb[q] && t < tb[q + 1]) s = q;
        g_sched[t][0] = s;
        if (s >= 0) {
            int ti = t - tb[s];
            #pragma unroll
            for (int j = 0; j < 4; j++) {
                int idx = ti * 4 + j;
                g_sched[t][1 + j] = (idx < cnt[s]) ? g_ord[base[s] + idx] : -1;
            }
        }
    }
}

// ---------------------------------------------------------------------------
// Convert x, w_in, w_out and interleave-pack w_ih to fp16 (natural order).
// Each thread: 8 contiguous elements -> one 16B store.
// ---------------------------------------------------------------------------
#define XR_E   (NROWS * IDIM)
#define WIN_E  (16 * HDIM * IDIM)
#define WOUT_E (16 * ODIM * HDIM)
#define WIH_E  (1536 * HDIM)
#define TOT_T  ((XR_E + WIN_E + WOUT_E + WIH_E) / 8)

__global__ void __launch_bounds__(256) k_cvt(
    const float4* __restrict__ x, const float4* __restrict__ w_in,
    const float* __restrict__ w_ih, const float4* __restrict__ w_out)
{
    int i = blockIdx.x * 256 + threadIdx.x;
    if (i >= TOT_T) return;
    float4 v0, v1; __half* dst; int e0;
    if (i < XR_E / 8) {
        e0 = i * 8; v0 = x[i*2]; v1 = x[i*2+1]; dst = g_xr;
    } else if (i < (XR_E + WIN_E) / 8) {
        int j = i - XR_E / 8; e0 = j * 8;
        v0 = w_in[j*2]; v1 = w_in[j*2+1]; dst = g_win;
    } else if (i < (XR_E + WIN_E + WOUT_E) / 8) {
        int j = i - (XR_E + WIN_E) / 8; e0 = j * 8;
        v0 = w_out[j*2]; v1 = w_out[j*2+1]; dst = g_wout;
    } else {
        int j = i - (XR_E + WIN_E + WOUT_E) / 8; e0 = j * 8;
        int p = e0 >> 9, c = e0 & 511;             // packed row p = 3h+gate
        int h = p / 3, gate = p - 3 * h;
        int sr = (gate == 0) ? h : (gate == 1) ? 1024 + h : 1536 + h;
        const float4* src = (const float4*)&w_ih[(size_t)sr * HDIM + c];
        v0 = src[0]; v1 = src[1]; dst = g_wih;
    }
    __half2 h2[4];
    h2[0] = __floats2half2_rn(v0.x, v0.y);
    h2[1] = __floats2half2_rn(v0.z, v0.w);
    h2[2] = __floats2half2_rn(v1.x, v1.y);
    h2[3] = __floats2half2_rn(v1.z, v1.w);
    *(uint4*)&dst[e0] = *(uint4*)h2;
}

// ---------------------------------------------------------------------------
// Pipelined fp16 m16n8k16 GEMM with ldmatrix fragment loads.
// SMEM: 144B row stride (128B data + 16B pad) -> LDSM phases hit all 32 banks;
// lane addresses are linear in kk (hoisted; +32B per kk).
// 8 warps: warp grid 2(M) x 4(N). 2-stage cp.async, 1 barrier per 64-k slab.
// MODE 0: xproj  BN=128 (warp 64x32), K=256: relu+bias -> g_xproj
// MODE 1: gates  BN=96  (warp 64x24), K=512: interleaved i/g/o; fused LSTM ->
//                h_out/c_out (fp32) + h1 -> g_h1
// MODE 2: logits BN=128 (warp 64x32), K=512: bias -> out (fp32)
// ---------------------------------------------------------------------------
#define ROWB 144

template <int MODE>
__global__ void __launch_bounds__(256, 2) k_gemm(
    const float* __restrict__ bias1, const float* __restrict__ bias2,
    float* __restrict__ Cout)
{
    constexpr int K = (MODE == 0) ? IDIM : HDIM;   // halves
    constexpr int NSLAB = K / 64;
    constexpr int BN = (MODE == 1) ? 96 : 128;
    constexpr int FN = (MODE == 1) ? 3 : 4;
    constexpr int WN = FN * 8;
    constexpr int ABYTES = 128 * ROWB;             // 18 KB
    constexpr int BBYTES = BN * ROWB;
    constexpr int STAGEB = ABYTES + BBYTES;

    extern __shared__ char smraw[];
    const uint32_t smbase = s2u(smraw);

    const int tid  = threadIdx.x;
    const int wid  = tid >> 5;
    const int lane = tid & 31;
    const int wm = wid >> 2;          // 0..1
    const int wn = wid & 3;           // 0..3
    const int lr = lane >> 2;         // 0..7
    const int lc = lane & 3;          // 0..3
    const int n0 = blockIdx.x * BN;

    int s = 0, m0 = 0;
    int aa[4] = {0, 0, 0, 0};
    int ab[4];
    const __half* Aptr;
    const __half* W;

    if (MODE == 1) {
        m0 = blockIdx.y * 128;
        ab[0] = m0; ab[1] = m0 + 32; ab[2] = m0 + 64; ab[3] = m0 + 96;
        Aptr = g_xproj;
        W = g_wih;
    } else {
        const int* t = g_sched[blockIdx.y];
        s = t[0];
        if (s < 0) return;
        int b0 = t[1];
        #pragma unroll
        for (int i = 0; i < 4; i++) {
            aa[i] = t[1 + i];
            ab[i] = ((aa[i] < 0) ? b0 : aa[i]) * 32;   // clamp pads (loads only)
        }
        Aptr = (MODE == 0) ? g_xr : g_h1;
        W = (MODE == 0) ? g_win + (size_t)s * HDIM * IDIM
                        : g_wout + (size_t)s * ODIM * HDIM;
    }

    auto load_slab = [&](int kt) {
        const int k0 = kt * 64;
        const uint32_t stb = smbase + (kt & 1) * STAGEB;
        #pragma unroll
        for (int i = 0; i < 4; i++) {              // A: 128 rows x 8 chunks (8 halves)
            int idx = tid + i * 256, r = idx >> 3, c = idx & 7;
            cp16(stb + r * ROWB + c * 16,
                 Aptr + (size_t)(ab[r >> 5] + (r & 31)) * K + k0 + c * 8);
        }
        #pragma unroll
        for (int i = 0; i < BN / 32; i++) {        // B: BN rows x 8 chunks
            int idx = tid + i * 256, r = idx >> 3, c = idx & 7;
            cp16(stb + ABYTES + r * ROWB + c * 16,
                 W + (size_t)(n0 + r) * K + k0 + c * 8);
        }
        asm volatile("cp.async.commit_group;");
    };

    // --- LDSM lane address offsets (linear; +32B per kk) ---
    // A x4 per fm: matrices (rows0-7,k0-7)(rows8-15,k0-7)(rows0-7,k8-15)(rows8-15,k8-15)
    const int aRow = (lane & 7) + ((lane >> 3) & 1) * 8;
    const int aK16 = (lane >> 4) * 16;
    uint32_t aoffL[4];
    #pragma unroll
    for (int fm = 0; fm < 4; fm++)
        aoffL[fm] = (uint32_t)((wm * 64 + fm * 16 + aRow) * ROWB + aK16);
    // B x4 per fn-pair: matrices (fn0,k0-7)(fn0,k8-15)(fn1,k0-7)(fn1,k8-15)
    const int bRowP = (lane & 7) + ((lane >> 4) & 1) * 8;
    const int bK16  = ((lane >> 3) & 1) * 16;
    uint32_t boffP0 = (uint32_t)(ABYTES + (wn * WN + bRowP) * ROWB + bK16);
    uint32_t boffP1 = boffP0 + 16 * ROWB;          // fns 2,3 (FN==4)
    // B x2 (FN==3, fn2): lanes 0-7 k0-7, lanes 8-15 k8-15
    uint32_t boff2  = (uint32_t)(ABYTES + (wn * WN + 16 + (lane & 7)) * ROWB + bK16);

    float acc[4][FN][4];
    #pragma unroll
    for (int a = 0; a < 4; a++)
        #pragma unroll
        for (int b = 0; b < FN; b++)
            #pragma unroll
            for (int c = 0; c < 4; c++) acc[a][b][c] = 0.0f;

    load_slab(0);

    for (int kt = 0; kt < NSLAB; kt++) {
        asm volatile("cp.async.wait_group 0;");
        __syncthreads();                           // data ready; prev compute done
        if (kt + 1 < NSLAB) load_slab(kt + 1);     // overlaps with compute below

        const uint32_t stb = smbase + (kt & 1) * STAGEB;

        #pragma unroll
        for (int kk = 0; kk < 4; kk++) {           // 16 k per kk
            const uint32_t kb = stb + kk * 32;
            unsigned af[4][4];
            #pragma unroll
            for (int fm = 0; fm < 4; fm++)
                ldsm_x4(af[fm], kb + aoffL[fm]);
            unsigned bf[FN][2];
            if (FN == 3) {
                unsigned t4[4];
                ldsm_x4(t4, kb + boffP0);
                bf[0][0] = t4[0]; bf[0][1] = t4[1];
                bf[1][0] = t4[2]; bf[1][1] = t4[3];
                ldsm_x2(bf[2], kb + boff2);
            } else {
                unsigned t4[4];
                ldsm_x4(t4, kb + boffP0);
                bf[0][0] = t4[0]; bf[0][1] = t4[1];
                bf[1][0] = t4[2]; bf[1][1] = t4[3];
                unsigned u4[4];
                ldsm_x4(u4, kb + boffP1);
                bf[2][0] = u4[0]; bf[2][1] = u4[1];
                bf[3][0] = u4[2]; bf[3][1] = u4[3];
            }
            #pragma unroll
            for (int fm = 0; fm < 4; fm++)
                #pragma unroll
                for (int fn = 0; fn < FN; fn++)
                    mma_f16(acc[fm][fn], af[fm], bf[fn]);
        }
    }

    // ------------------------------ Epilogue -------------------------------
    if (MODE == 1) {
        __syncthreads();                           // stages free for scratch
        float* scr = (float*)smraw + wid * (64 * 25);   // 64 rows x 24 cols pad 25
        #pragma unroll
        for (int fm = 0; fm < 4; fm++) {
            int rr0 = fm * 16 + lr;
            #pragma unroll
            for (int fn = 0; fn < FN; fn++) {
                int cc = fn * 8 + lc * 2;
                scr[rr0 * 25 + cc]            = acc[fm][fn][0];
                scr[rr0 * 25 + cc + 1]        = acc[fm][fn][1];
                scr[(rr0 + 8) * 25 + cc]      = acc[fm][fn][2];
                scr[(rr0 + 8) * 25 + cc + 1]  = acc[fm][fn][3];
            }
        }
        __syncwarp();
        const int hb = (n0 + wn * WN) / 3;         // 8 h per warp window
        const int rowb = m0 + wm * 64;
        #pragma unroll
        for (int it = 0; it < 16; it++) {
            int item = it * 32 + lane;             // 64 rows x 8 h
            int rr = item >> 3, hh = item & 7;
            int h = hb + hh;
            float gi = scr[rr * 25 + hh * 3    ] + bias1[h]        + bias2[h];
            float gg = scr[rr * 25 + hh * 3 + 1] + bias1[1024 + h] + bias2[1024 + h];
            float go = scr[rr * 25 + hh * 3 + 2] + bias1[1536 + h] + bias2[1536 + h];
            float c1 = sigmoidf_(gi) * tanhf(gg);  // f*c0 == 0
            float h1 = sigmoidf_(go) * tanhf(c1);
            size_t row = (size_t)(rowb + rr);
            Cout[H_OFF + row * HDIM + h] = h1;
            Cout[C_OFF + row * HDIM + h] = c1;
            g_h1[row * HDIM + h] = __float2half(h1);
        }
    } else {
        #pragma unroll
        for (int fm = 0; fm < 4; fm++) {
            int rl = wm * 64 + fm * 16 + lr;
            int grp = rl >> 5;
            if (aa[grp] < 0) continue;
            size_t grow0 = (size_t)aa[grp] * 32 + (rl & 31);
            size_t grow1 = grow0 + 8;
            #pragma unroll
            for (int fn = 0; fn < FN; fn++) {
                int col = n0 + wn * WN + fn * 8 + lc * 2;
                float v00 = acc[fm][fn][0], v01 = acc[fm][fn][1];
                float v10 = acc[fm][fn][2], v11 = acc[fm][fn][3];
                if (MODE == 0) {
                    float b0 = bias1[s * HDIM + col], b1 = bias1[s * HDIM + col + 1];
                    *(__half2*)&g_xproj[grow0 * HDIM + col] =
                        __floats2half2_rn(fmaxf(v00 + b0, 0.0f), fmaxf(v01 + b1, 0.0f));
                    *(__half2*)&g_xproj[grow1 * HDIM + col] =
                        __floats2half2_rn(fmaxf(v10 + b0, 0.0f), fmaxf(v11 + b1, 0.0f));
                } else {
                    float b0 = bias1[s * ODIM + col], b1 = bias1[s * ODIM + col + 1];
                    Cout[grow0 * ODIM + col    ] = v00 + b0;
                    Cout[grow0 * ODIM + col + 1] = v01 + b1;
                    Cout[grow1 * ODIM + col    ] = v10 + b0;
                    Cout[grow1 * ODIM + col + 1] = v11 + b1;
                }
            }
        }
    }
}

// ---------------------------------------------------------------------------
// inputs: 0 x, 1 species, 2 w_in, 3 b_in, 4 w_ih, 5 w_hh(unused), 6 b_ih,
//         7 b_hh, 8 w_out, 9 b_out
// ---------------------------------------------------------------------------
extern "C" void kernel_launch(void* const* d_in, const int* in_sizes, int n_in,
                              void* d_out, int out_size)
{
    const float* x     = (const float*)d_in[0];
    const int*   sp    = (const int*)d_in[1];
    const float* w_in  = (const float*)d_in[2];
    const float* b_in  = (const float*)d_in[3];
    const float* w_ih  = (const float*)d_in[4];
    const float* b_ih  = (const float*)d_in[6];
    const float* b_hh  = (const float*)d_in[7];
    const float* w_out = (const float*)d_in[8];
    const float* b_out = (const float*)d_in[9];
    float* out = (float*)d_out;

    const int SMEM02 = 2 * (128 * ROWB + 128 * ROWB);   // 72 KB
    const int SMEM1  = 2 * (128 * ROWB + 96 * ROWB);    // 63 KB

    static bool attr_done = false;
    if (!attr_done) {
        cudaFuncSetAttribute(k_gemm<0>, cudaFuncAttributeMaxDynamicSharedMemorySize, SMEM02);
        cudaFuncSetAttribute(k_gemm<1>, cudaFuncAttributeMaxDynamicSharedMemorySize, SMEM1);
        cudaFuncSetAttribute(k_gemm<2>, cudaFuncAttributeMaxDynamicSharedMemorySize, SMEM02);
        attr_done = true;
    }

    k_build<<<1, 512>>>(sp);

    k_cvt<<<(TOT_T + 255) / 256, 256>>>(
        (const float4*)x, (const float4*)w_in, w_ih, (const float4*)w_out);

    // xproj: N=512 -> 4 tiles of 128, species-scheduled M tiles
    k_gemm<0><<<dim3(4, MAX_TILES), 256, SMEM02>>>(b_in, nullptr, nullptr);

    // gates (interleaved 3h+gate, fused LSTM): N=1536 -> 16 tiles of 96
    k_gemm<1><<<dim3(16, NROWS / 128), 256, SMEM1>>>(b_ih, b_hh, out);

    // logits: N=1024 -> 8 tiles of 128, species-scheduled M tiles
    k_gemm<2><<<dim3(8, MAX_TILES), 256, SMEM02>>>(b_out, nullptr, out);
}